// round 3
// baseline (speedup 1.0000x reference)
#include <cuda_runtime.h>
#include <cuda_bf16.h>
#include <math.h>

// Problem constants
constexpr int Bb  = 4;
constexpr int LP  = 768;
constexpr int LE  = 256;
constexpr int Lt  = 1024;   // LP + LE
constexpr int DP  = 2048;
constexpr int DE  = 1024;
constexpr int Hh  = 8;
constexpr int HD  = 256;
constexpr int HH  = 2048;   // H * HD

// Scratch (allocation-free: static device globals)
__device__ float g_Q[(size_t)Bb * Lt * HH];        // 8.4M floats
__device__ float g_K[(size_t)Bb * Lt * HD];        // 1M
__device__ float g_V[(size_t)Bb * Lt * HD];        // 1M
__device__ float g_S[(size_t)Bb * Hh * Lt * Lt];   // 33.5M (scores / probs)
__device__ float g_AO[(size_t)Bb * Lt * HH];       // 8.4M (attention output)

// ---------------------------------------------------------------------------
// Tiled SGEMM core: 128x128 block tile, BK=8, 256 threads, 8x8 per thread.
// TRANS_B: B is [N,K] row-major (dot of rows) instead of [K,N].
// EPI_MASK: C = acc*scale + mask[m, n]  (mask row-major with ld=ldm)
// Assumes M%128==0, N%128==0, K%8==0, all pointers 16B aligned, lds %4==0.
// ---------------------------------------------------------------------------
constexpr int BM = 128, BN = 128, BK = 8, TM = 8, TN = 8;

template <bool TRANS_B, bool EPI_MASK>
__device__ __forceinline__ void gemm_tile(
    const float* __restrict__ A, const float* __restrict__ B, float* __restrict__ C,
    int K, int lda, int ldb, int ldc,
    float scale, const float* __restrict__ mask, int ldm)
{
    __shared__ float As[BK][BM + 4];
    __shared__ float Bs[BK][BN + 4];

    const int tid = threadIdx.x;          // 0..255
    const int tx  = tid & 15;             // 0..15
    const int ty  = tid >> 4;             // 0..15

    const long long brow = (long long)blockIdx.y * BM;
    const long long bcol = (long long)blockIdx.x * BN;

    // A-load mapping: 128 rows x 8 cols, float4 per thread
    const int arow = tid >> 1;            // 0..127
    const int acol = (tid & 1) * 4;       // 0 or 4
    // B-load mapping (NN): 8 rows x 128 cols
    const int bkr = tid >> 5;             // 0..7
    const int bnc = (tid & 31) * 4;       // 0..124

    float acc[TM][TN];
#pragma unroll
    for (int i = 0; i < TM; i++)
#pragma unroll
        for (int j = 0; j < TN; j++) acc[i][j] = 0.0f;

    for (int k0 = 0; k0 < K; k0 += BK) {
        // Stage A (transposed into As[k][m])
        float4 av = *reinterpret_cast<const float4*>(
            A + (brow + arow) * (long long)lda + k0 + acol);
        As[acol + 0][arow] = av.x;
        As[acol + 1][arow] = av.y;
        As[acol + 2][arow] = av.z;
        As[acol + 3][arow] = av.w;

        if (TRANS_B) {
            float4 bv = *reinterpret_cast<const float4*>(
                B + (bcol + arow) * (long long)ldb + k0 + acol);
            Bs[acol + 0][arow] = bv.x;
            Bs[acol + 1][arow] = bv.y;
            Bs[acol + 2][arow] = bv.z;
            Bs[acol + 3][arow] = bv.w;
        } else {
            float4 bv = *reinterpret_cast<const float4*>(
                B + (long long)(k0 + bkr) * ldb + bcol + bnc);
            Bs[bkr][bnc + 0] = bv.x;
            Bs[bkr][bnc + 1] = bv.y;
            Bs[bkr][bnc + 2] = bv.z;
            Bs[bkr][bnc + 3] = bv.w;
        }
        __syncthreads();

#pragma unroll
        for (int kk = 0; kk < BK; kk++) {
            float a[TM], b[TN];
#pragma unroll
            for (int i = 0; i < TM; i++) a[i] = As[kk][ty * TM + i];
#pragma unroll
            for (int j = 0; j < TN; j++) b[j] = Bs[kk][tx * TN + j];
#pragma unroll
            for (int i = 0; i < TM; i++)
#pragma unroll
                for (int j = 0; j < TN; j++)
                    acc[i][j] = fmaf(a[i], b[j], acc[i][j]);
        }
        __syncthreads();
    }

    // Epilogue
#pragma unroll
    for (int i = 0; i < TM; i++) {
        long long row = brow + ty * TM + i;
        long long col = bcol + tx * TN;
        float4 v0, v1;
        if (EPI_MASK) {
            const float* mrow = mask + row * (long long)ldm + col;
            v0.x = acc[i][0] * scale + mrow[0];
            v0.y = acc[i][1] * scale + mrow[1];
            v0.z = acc[i][2] * scale + mrow[2];
            v0.w = acc[i][3] * scale + mrow[3];
            v1.x = acc[i][4] * scale + mrow[4];
            v1.y = acc[i][5] * scale + mrow[5];
            v1.z = acc[i][6] * scale + mrow[6];
            v1.w = acc[i][7] * scale + mrow[7];
        } else {
            v0.x = acc[i][0]; v0.y = acc[i][1]; v0.z = acc[i][2]; v0.w = acc[i][3];
            v1.x = acc[i][4]; v1.y = acc[i][5]; v1.z = acc[i][6]; v1.w = acc[i][7];
        }
        float* crow = C + row * (long long)ldc + col;
        *reinterpret_cast<float4*>(crow)     = v0;
        *reinterpret_cast<float4*>(crow + 4) = v1;
    }
}

// Generic NN GEMM with per-z pointer strides (projections)
__global__ void __launch_bounds__(256)
sgemm_nn_kernel(const float* __restrict__ A, const float* __restrict__ B,
                float* __restrict__ C, int K, int lda, int ldb, int ldc,
                long long sA, long long sB, long long sC)
{
    gemm_tile<false, false>(A + blockIdx.z * sA, B + blockIdx.z * sB,
                            C + blockIdx.z * sC, K, lda, ldb, ldc,
                            1.0f, nullptr, 0);
}

// scores[b,h,q,k] = scale * Q[b,q,h,:]·K[b,k,:] + mask[b,q,k]
__global__ void __launch_bounds__(256)
attn_scores_kernel(const float* __restrict__ Q, const float* __restrict__ Kb,
                   const float* __restrict__ mask, float* __restrict__ S)
{
    int z = blockIdx.z;          // b*H + h
    int b = z >> 3;
    int h = z & 7;
    gemm_tile<true, true>(
        Q + (long long)b * Lt * HH + (long long)h * HD,
        Kb + (long long)b * Lt * HD,
        S + (long long)z * Lt * Lt,
        HD, HH, HD, Lt,
        0.0625f /* 1/sqrt(256) */,
        mask + (long long)b * Lt * Lt, Lt);
}

// AO[b,q,h,:] = P[b,h,q,:] @ V[b,:,:]
__global__ void __launch_bounds__(256)
attn_pv_kernel(const float* __restrict__ S, const float* __restrict__ V,
               float* __restrict__ AO)
{
    int z = blockIdx.z;
    int b = z >> 3;
    int h = z & 7;
    gemm_tile<false, false>(
        S + (long long)z * Lt * Lt,
        V + (long long)b * Lt * HD,
        AO + (long long)b * Lt * HH + (long long)h * HD,
        Lt, Lt, HD, HH,
        1.0f, nullptr, 0);
}

// ---------------------------------------------------------------------------
// RoPE (Gemma half-split) applied in place to Q (all heads) and K (1 kv head).
// One block per (b,l), 128 threads (= HD/2).
// ---------------------------------------------------------------------------
__global__ void __launch_bounds__(128)
rope_kernel(float* __restrict__ Q, float* __restrict__ Kb,
            const int* __restrict__ pos)
{
    const int bl = blockIdx.x;               // b*Lt + l
    const int i  = threadIdx.x;              // 0..127
    const float p = (float)pos[bl];
    // inv_freq = 10000^(-i/128)
    const float inv = powf(10000.0f, -(float)i * (1.0f / 128.0f));
    const float f = p * inv;
    float s, c;
    sincosf(f, &s, &c);

    // Q: 8 heads
    float* qb = Q + (long long)bl * HH;
#pragma unroll
    for (int h = 0; h < Hh; h++) {
        float x1 = qb[h * HD + i];
        float x2 = qb[h * HD + 128 + i];
        qb[h * HD + i]       = x1 * c - x2 * s;
        qb[h * HD + 128 + i] = x2 * c + x1 * s;
    }
    // K: 1 kv head
    float* kb = Kb + (long long)bl * HD;
    float x1 = kb[i];
    float x2 = kb[128 + i];
    kb[i]       = x1 * c - x2 * s;
    kb[128 + i] = x2 * c + x1 * s;
}

// ---------------------------------------------------------------------------
// Row softmax over S: B*H*Lt rows of length Lt. Block(256) per row.
// ---------------------------------------------------------------------------
__global__ void __launch_bounds__(256)
softmax_kernel(float* __restrict__ S)
{
    __shared__ float red[256];
    float* p = S + (long long)blockIdx.x * Lt;
    const int t = threadIdx.x;

    float x0 = p[t], x1 = p[t + 256], x2 = p[t + 512], x3 = p[t + 768];

    float m = fmaxf(fmaxf(x0, x1), fmaxf(x2, x3));
    red[t] = m;
    __syncthreads();
    for (int s = 128; s > 0; s >>= 1) {
        if (t < s) red[t] = fmaxf(red[t], red[t + s]);
        __syncthreads();
    }
    m = red[0];
    __syncthreads();

    x0 = expf(x0 - m); x1 = expf(x1 - m); x2 = expf(x2 - m); x3 = expf(x3 - m);
    red[t] = x0 + x1 + x2 + x3;
    __syncthreads();
    for (int s = 128; s > 0; s >>= 1) {
        if (t < s) red[t] += red[t + s];
        __syncthreads();
    }
    const float inv = 1.0f / red[0];

    p[t]       = x0 * inv;
    p[t + 256] = x1 * inv;
    p[t + 512] = x2 * inv;
    p[t + 768] = x3 * inv;
}

// ---------------------------------------------------------------------------
// Host launcher
// ---------------------------------------------------------------------------
static inline void launch_nn(const float* A, const float* B, float* C,
                             int M, int N, int K, int lda, int ldb, int ldc,
                             long long sA, long long sB, long long sC, int Z)
{
    dim3 grid(N / BN, M / BM, Z);
    sgemm_nn_kernel<<<grid, 256>>>(A, B, C, K, lda, ldb, ldc, sA, sB, sC);
}

extern "C" void kernel_launch(void* const* d_in, const int* in_sizes, int n_in,
                              void* d_out, int out_size)
{
    const float* pali   = (const float*)d_in[0];
    const float* expert = (const float*)d_in[1];
    const int*   pos    = (const int*)d_in[2];
    const float* mask   = (const float*)d_in[3];
    // d_in[4] = use_cache (always 0 here, prefill path) — ignored
    const float* wq_p = (const float*)d_in[5];
    const float* wk_p = (const float*)d_in[6];
    const float* wv_p = (const float*)d_in[7];
    const float* wo_p = (const float*)d_in[8];
    const float* wq_e = (const float*)d_in[9];
    const float* wk_e = (const float*)d_in[10];
    const float* wv_e = (const float*)d_in[11];
    const float* wo_e = (const float*)d_in[12];

    float* out   = (float*)d_out;
    float* out_p = out;
    float* out_e = out + (long long)Bb * LP * DP;

    float *Q, *K, *V, *S, *AO;
    cudaGetSymbolAddress((void**)&Q,  g_Q);
    cudaGetSymbolAddress((void**)&K,  g_K);
    cudaGetSymbolAddress((void**)&V,  g_V);
    cudaGetSymbolAddress((void**)&S,  g_S);
    cudaGetSymbolAddress((void**)&AO, g_AO);

    // --- QKV projections (pali stream: rows [0,768), expert: rows [768,1024)) ---
    // pali
    launch_nn(pali, wq_p, Q, LP, HH, DP, DP, HH, HH,
              (long long)LP * DP, 0, (long long)Lt * HH, Bb);
    launch_nn(pali, wk_p, K, LP, HD, DP, DP, HD, HD,
              (long long)LP * DP, 0, (long long)Lt * HD, Bb);
    launch_nn(pali, wv_p, V, LP, HD, DP, DP, HD, HD,
              (long long)LP * DP, 0, (long long)Lt * HD, Bb);
    // expert
    launch_nn(expert, wq_e, Q + (long long)LP * HH, LE, HH, DE, DE, HH, HH,
              (long long)LE * DE, 0, (long long)Lt * HH, Bb);
    launch_nn(expert, wk_e, K + (long long)LP * HD, LE, HD, DE, DE, HD, HD,
              (long long)LE * DE, 0, (long long)Lt * HD, Bb);
    launch_nn(expert, wv_e, V + (long long)LP * HD, LE, HD, DE, DE, HD, HD,
              (long long)LE * DE, 0, (long long)Lt * HD, Bb);

    // --- RoPE on Q and K ---
    rope_kernel<<<Bb * Lt, 128>>>(Q, K, pos);

    // --- scores = scale * Q K^T + mask ---
    {
        dim3 grid(Lt / BN, Lt / BM, Bb * Hh);
        attn_scores_kernel<<<grid, 256>>>(Q, K, mask, S);
    }

    // --- softmax over k ---
    softmax_kernel<<<Bb * Hh * Lt, 256>>>(S);

    // --- AO = P @ V ---
    {
        dim3 grid(HD / BN, Lt / BM, Bb * Hh);
        attn_pv_kernel<<<grid, 256>>>(S, V, AO);
    }

    // --- output projections ---
    launch_nn(AO, wo_p, out_p, LP, DP, HH, HH, DP, DP,
              (long long)Lt * HH, 0, (long long)LP * DP, Bb);
    launch_nn(AO + (long long)LP * HH, wo_e, out_e, LE, DE, HH, HH, DE, DE,
              (long long)Lt * HH, 0, (long long)LE * DE, Bb);
}

// round 5
// speedup vs baseline: 5.1713x; 5.1713x over previous
#include <cuda_runtime.h>
#include <cuda_fp16.h>
#include <math.h>
#include <stdint.h>

constexpr int Bb = 4, LP = 768, LE = 256, Lt = 1024;
constexpr int DP = 2048, DE = 1024, Hh = 8, HD = 256, HH = 2048;
constexpr int NQKV = HH + 2 * HD;  // 2560

// fp32 scratch
__device__ __align__(1024) float g_QKV[(size_t)Bb * Lt * NQKV];
__device__ __align__(1024) float g_S[(size_t)Bb * Hh * Lt * Lt];
__device__ __align__(1024) float g_AO[(size_t)Bb * Lt * HH];

// packed fp16 operands, K-major rows [R][2K] (hi | lo-or-hi)
__device__ __align__(1024) __half hA_pali[(size_t)Bb * LP * 4096];
__device__ __align__(1024) __half hA_exp [(size_t)Bb * LE * 2048];
__device__ __align__(1024) __half hA_Q   [(size_t)Bb * Hh * Lt * 512];
__device__ __align__(1024) __half hA_P   [(size_t)Bb * Hh * Lt * 2048];
__device__ __align__(1024) __half hA_AOp [(size_t)Bb * LP * 4096];
__device__ __align__(1024) __half hA_AOe [(size_t)Bb * LE * 4096];
__device__ __align__(1024) __half hB_qkvp[(size_t)NQKV * 4096];
__device__ __align__(1024) __half hB_qkve[(size_t)NQKV * 2048];
__device__ __align__(1024) __half hB_K   [(size_t)Bb * Lt * 512];
__device__ __align__(1024) __half hB_V   [(size_t)Bb * HD * 2048];
__device__ __align__(1024) __half hB_wop [(size_t)DP * 4096];
__device__ __align__(1024) __half hB_woe [(size_t)DE * 4096];

__device__ __forceinline__ uint32_t s2u(const void* p) {
    uint32_t a;
    asm("{ .reg .u64 t; cvta.to.shared.u64 t, %1; cvt.u32.u64 %0, t; }" : "=r"(a) : "l"(p));
    return a;
}

#define CP_ASYNC16(saddr, gaddr) \
    asm volatile("cp.async.cg.shared.global [%0], [%1], 16;" :: "r"(saddr), "l"(gaddr))
#define CP_COMMIT() asm volatile("cp.async.commit_group;")
#define CP_WAIT(n)  asm volatile("cp.async.wait_group %0;" :: "n"(n))

#define LDSM4(r, addr)                                                       \
    asm volatile("ldmatrix.sync.aligned.m8n8.x4.shared.b16 {%0,%1,%2,%3}, [%4];" \
        : "=r"((r)[0]), "=r"((r)[1]), "=r"((r)[2]), "=r"((r)[3]) : "r"(addr))

#define MMA16816(c, a, b0, b1)                                               \
    asm volatile("mma.sync.aligned.m16n8k16.row.col.f32.f16.f16.f32 "        \
        "{%0,%1,%2,%3},{%4,%5,%6,%7},{%8,%9},{%0,%1,%2,%3};"                 \
        : "+f"((c)[0]), "+f"((c)[1]), "+f"((c)[2]), "+f"((c)[3])             \
        : "r"((a)[0]), "r"((a)[1]), "r"((a)[2]), "r"((a)[3]), "r"(b0), "r"(b1))

// ---------------------------------------------------------------------------
// HMMA GEMM (TN): C[M,N] = sum_k A[m,k]*B[n,k]. A,B fp16 K-major [R][Kaug].
// 128x128 block tile, BK=64, 256 thr (8 warps of 32x64), double-buffered
// cp.async staging with XOR-swizzled smem. Optional C = acc*scale + mask.
// ---------------------------------------------------------------------------
constexpr int GEMM_SMEM = 65536;  // 2 stages x (16KB A + 16KB B)

__global__ void __launch_bounds__(256, 2) gemm_hmma(
    const __half* __restrict__ Ap, const __half* __restrict__ Bp,
    float* __restrict__ C, const float* __restrict__ mask,
    int Kaug, long long sAz, long long sBz, int zshB,
    long long cso, long long csi, int czsh, int ldc,
    float scale, int use_mask, long long mzs)
{
    extern __shared__ __align__(1024) char smem[];
    const uint32_t sbase = s2u(smem);
    const int t = threadIdx.x;
    const int z = blockIdx.z;

    const __half* Ag = Ap + (long long)z * sAz + (long long)blockIdx.y * 128 * Kaug;
    const __half* Bg = Bp + (long long)(z >> zshB) * sBz + (long long)blockIdx.x * 128 * Kaug;

    const int lrow = t >> 3, lc = t & 7;  // staging: (row, 16B-chunk)

    float acc[2][8][4];
#pragma unroll
    for (int i = 0; i < 2; i++)
#pragma unroll
        for (int j = 0; j < 8; j++)
#pragma unroll
            for (int k = 0; k < 4; k++) acc[i][j][k] = 0.f;

    const int nch = Kaug >> 6;

    // stage(s, k0)
#define STAGE(s, k0) do {                                                    \
    uint32_t _sA = sbase + (s) * 32768;                                      \
    uint32_t _sB = _sA + 16384;                                              \
    _Pragma("unroll")                                                        \
    for (int _i = 0; _i < 4; _i++) {                                         \
        int _r = lrow + _i * 32;                                             \
        uint32_t _sw = ((uint32_t)(lc ^ (_r & 7))) << 4;                     \
        CP_ASYNC16(_sA + _r * 128 + _sw, Ag + (long long)_r * Kaug + (k0) + lc * 8); \
        CP_ASYNC16(_sB + _r * 128 + _sw, Bg + (long long)_r * Kaug + (k0) + lc * 8); \
    }                                                                        \
    CP_COMMIT();                                                             \
} while (0)

    STAGE(0, 0);

    const int wid = t >> 5, lane = t & 31;
    const int wm = wid >> 1, wn = wid & 1;
    const int a_r = lane & 15, a_c = lane >> 4;
    const int b_r = (lane & 7) + ((lane >> 4) << 3), b_c = (lane >> 3) & 1;

    for (int ch = 0; ch < nch; ch++) {
        if (ch + 1 < nch) { STAGE((ch + 1) & 1, (ch + 1) << 6); CP_WAIT(1); }
        else              { CP_WAIT(0); }
        __syncthreads();
        uint32_t sA = sbase + (ch & 1) * 32768;
        uint32_t sB = sA + 16384;
#pragma unroll
        for (int ks = 0; ks < 4; ks++) {
            const int kc = ks << 1;  // 16B-chunk index of this k16
            uint32_t a[2][4];
#pragma unroll
            for (int mt = 0; mt < 2; mt++) {
                int r = wm * 32 + mt * 16 + a_r;
                LDSM4(a[mt], sA + r * 128 + ((uint32_t)((kc + a_c) ^ (r & 7)) << 4));
            }
            uint32_t b[4][4];
#pragma unroll
            for (int nt2 = 0; nt2 < 4; nt2++) {
                int n = wn * 64 + nt2 * 16 + b_r;
                LDSM4(b[nt2], sB + n * 128 + ((uint32_t)((kc + b_c) ^ (n & 7)) << 4));
            }
#pragma unroll
            for (int mt = 0; mt < 2; mt++)
#pragma unroll
                for (int nt = 0; nt < 8; nt++)
                    MMA16816(acc[mt][nt], a[mt], b[nt >> 1][(nt & 1) * 2], b[nt >> 1][(nt & 1) * 2 + 1]);
        }
        __syncthreads();
    }

    // epilogue
    const long long coff = ((long long)(z >> czsh)) * cso +
                           (long long)(z & ((1 << czsh) - 1)) * csi;
    const int g = lane >> 2, tig = lane & 3;
#pragma unroll
    for (int mt = 0; mt < 2; mt++) {
#pragma unroll
        for (int h2 = 0; h2 < 2; h2++) {
            long long row = (long long)blockIdx.y * 128 + wm * 32 + mt * 16 + g + h2 * 8;
            long long cb = row * (long long)ldc + (long long)blockIdx.x * 128 + wn * 64 + tig * 2;
            float* crow = C + coff + cb;
            const float* mrow = use_mask ? (mask + (long long)(z >> 3) * mzs + cb) : nullptr;
#pragma unroll
            for (int nt = 0; nt < 8; nt++) {
                float v0 = acc[mt][nt][h2 * 2 + 0];
                float v1 = acc[mt][nt][h2 * 2 + 1];
                if (use_mask) { v0 = v0 * scale + mrow[nt * 8]; v1 = v1 * scale + mrow[nt * 8 + 1]; }
                *reinterpret_cast<float2*>(crow + nt * 8) = make_float2(v0, v1);
            }
        }
    }
#undef STAGE
}

// ---------------------------------------------------------------------------
// Pack fp32 -> fp16 [z][R][2K]: part0 = hi; part1 = (aside ? lo : hi)
// ---------------------------------------------------------------------------
template <bool KC>
__global__ void __launch_bounds__(256) pack_kernel(
    const float* __restrict__ src, __half* __restrict__ dst,
    int R, int Kp, long long rs, long long ks,
    int zdiv, long long zso, long long zsi, int aside, long long total)
{
    long long idx = (long long)blockIdx.x * 256 + threadIdx.x;
    if (idx >= total) return;
    int K8 = Kp >> 3;
    int kc = (int)(idx % K8); long long tt = idx / K8;
    int part = (int)(tt & 1); tt >>= 1;
    int r = (int)(tt % R);
    int z = (int)(tt / R);
    int kk = kc * 8;

    const float* sp = src + (long long)(z / zdiv) * zso + (long long)(z % zdiv) * zsi
                          + (long long)r * rs;
    float v[8];
    if (KC) {
        float4 x = *reinterpret_cast<const float4*>(sp + kk);
        float4 y = *reinterpret_cast<const float4*>(sp + kk + 4);
        v[0]=x.x; v[1]=x.y; v[2]=x.z; v[3]=x.w; v[4]=y.x; v[5]=y.y; v[6]=y.z; v[7]=y.w;
    } else {
#pragma unroll
        for (int i = 0; i < 8; i++) v[i] = sp[(long long)(kk + i) * ks];
    }
    unsigned short o[8];
#pragma unroll
    for (int i = 0; i < 8; i++) {
        __half h = __float2half_rn(v[i]);
        if (part && aside) h = __float2half_rn(v[i] - __half2float(h));
        o[i] = __half_as_ushort(h);
    }
    uint4 w;
    w.x = (uint32_t)o[0] | ((uint32_t)o[1] << 16);
    w.y = (uint32_t)o[2] | ((uint32_t)o[3] << 16);
    w.z = (uint32_t)o[4] | ((uint32_t)o[5] << 16);
    w.w = (uint32_t)o[6] | ((uint32_t)o[7] << 16);
    __half* dp = dst + ((long long)z * R + r) * (2LL * Kp) + (long long)part * Kp + kk;
    *reinterpret_cast<uint4*>(dp) = w;
}

// ---------------------------------------------------------------------------
// RoPE on fused QKV (Q cols [0,2048), K cols [2048,2304))
// ---------------------------------------------------------------------------
__global__ void __launch_bounds__(128) rope_kernel(float* __restrict__ QKV,
                                                   const int* __restrict__ pos)
{
    const int bl = blockIdx.x, i = threadIdx.x;
    const float p = (float)pos[bl];
    const float inv = powf(10000.0f, -(float)i * (1.0f / 128.0f));
    float s, c;
    sincosf(p * inv, &s, &c);
    float* qb = QKV + (long long)bl * NQKV;
#pragma unroll
    for (int h = 0; h < Hh; h++) {
        float x1 = qb[h * HD + i], x2 = qb[h * HD + 128 + i];
        qb[h * HD + i]       = x1 * c - x2 * s;
        qb[h * HD + 128 + i] = x2 * c + x1 * s;
    }
    float* kb = qb + HH;
    float x1 = kb[i], x2 = kb[128 + i];
    kb[i]       = x1 * c - x2 * s;
    kb[128 + i] = x2 * c + x1 * s;
}

// ---------------------------------------------------------------------------
// Softmax over S rows (len 1024) + write packed fp16 P [z][q][hi(1024)|lo(1024)]
// ---------------------------------------------------------------------------
__global__ void __launch_bounds__(128) softmax_pack(const float* __restrict__ S,
                                                    __half* __restrict__ P)
{
    __shared__ float red[128];
    const long long rowid = blockIdx.x;
    const float* p = S + rowid * Lt;
    const int t = threadIdx.x, k0 = t * 8;

    float v[8];
    float4 a = *reinterpret_cast<const float4*>(p + k0);
    float4 b = *reinterpret_cast<const float4*>(p + k0 + 4);
    v[0]=a.x; v[1]=a.y; v[2]=a.z; v[3]=a.w; v[4]=b.x; v[5]=b.y; v[6]=b.z; v[7]=b.w;

    float m = v[0];
#pragma unroll
    for (int i = 1; i < 8; i++) m = fmaxf(m, v[i]);
    red[t] = m; __syncthreads();
    for (int s = 64; s > 0; s >>= 1) { if (t < s) red[t] = fmaxf(red[t], red[t + s]); __syncthreads(); }
    m = red[0]; __syncthreads();

    float sum = 0.f;
#pragma unroll
    for (int i = 0; i < 8; i++) { v[i] = expf(v[i] - m); sum += v[i]; }
    red[t] = sum; __syncthreads();
    for (int s = 64; s > 0; s >>= 1) { if (t < s) red[t] += red[t + s]; __syncthreads(); }
    const float invs = 1.0f / red[0];

    unsigned short hi[8], lo[8];
#pragma unroll
    for (int i = 0; i < 8; i++) {
        float x = v[i] * invs;
        __half h = __float2half_rn(x);
        __half l = __float2half_rn(x - __half2float(h));
        hi[i] = __half_as_ushort(h);
        lo[i] = __half_as_ushort(l);
    }
    uint4 whi, wlo;
    whi.x = (uint32_t)hi[0] | ((uint32_t)hi[1] << 16);
    whi.y = (uint32_t)hi[2] | ((uint32_t)hi[3] << 16);
    whi.z = (uint32_t)hi[4] | ((uint32_t)hi[5] << 16);
    whi.w = (uint32_t)hi[6] | ((uint32_t)hi[7] << 16);
    wlo.x = (uint32_t)lo[0] | ((uint32_t)lo[1] << 16);
    wlo.y = (uint32_t)lo[2] | ((uint32_t)lo[3] << 16);
    wlo.z = (uint32_t)lo[4] | ((uint32_t)lo[5] << 16);
    wlo.w = (uint32_t)lo[6] | ((uint32_t)lo[7] << 16);

    __half* base = P + rowid * 2048 + k0;
    *reinterpret_cast<uint4*>(base)        = whi;
    *reinterpret_cast<uint4*>(base + 1024) = wlo;
}

// ---------------------------------------------------------------------------
// Host launchers
// ---------------------------------------------------------------------------
template <bool KC>
static void launch_pack(const float* src, __half* dst, int R, int Kp,
                        long long rs, long long ks, int zdiv,
                        long long zso, long long zsi, int aside, int Z)
{
    long long total = (long long)Z * R * 2 * (Kp / 8);
    pack_kernel<KC><<<(int)((total + 255) / 256), 256>>>(
        src, dst, R, Kp, rs, ks, zdiv, zso, zsi, aside, total);
}

static void launch_gemm(const __half* A, const __half* B, float* C, const float* mask,
                        int nt, int mt, int Z, int Kaug, long long sAz, long long sBz,
                        int zshB, long long cso, long long csi, int czsh, int ldc,
                        float scale, int use_mask, long long mzs)
{
    dim3 grid(nt, mt, Z);
    gemm_hmma<<<grid, 256, GEMM_SMEM>>>(A, B, C, mask, Kaug, sAz, sBz, zshB,
                                        cso, csi, czsh, ldc, scale, use_mask, mzs);
}

extern "C" void kernel_launch(void* const* d_in, const int* in_sizes, int n_in,
                              void* d_out, int out_size)
{
    const float* pali   = (const float*)d_in[0];
    const float* expert = (const float*)d_in[1];
    const int*   pos    = (const int*)d_in[2];
    const float* mask   = (const float*)d_in[3];
    const float* wq_p = (const float*)d_in[5];
    const float* wk_p = (const float*)d_in[6];
    const float* wv_p = (const float*)d_in[7];
    const float* wo_p = (const float*)d_in[8];
    const float* wq_e = (const float*)d_in[9];
    const float* wk_e = (const float*)d_in[10];
    const float* wv_e = (const float*)d_in[11];
    const float* wo_e = (const float*)d_in[12];
    float* out = (float*)d_out;

    cudaFuncSetAttribute(gemm_hmma, cudaFuncAttributeMaxDynamicSharedMemorySize, GEMM_SMEM);

    float *QKV, *S, *AO;
    cudaGetSymbolAddress((void**)&QKV, g_QKV);
    cudaGetSymbolAddress((void**)&S,   g_S);
    cudaGetSymbolAddress((void**)&AO,  g_AO);
    __half *aP, *aE, *aQ, *aPP, *aAOp, *aAOe, *bQP, *bQE, *bK, *bV, *bWP, *bWE;
    cudaGetSymbolAddress((void**)&aP,  hA_pali);
    cudaGetSymbolAddress((void**)&aE,  hA_exp);
    cudaGetSymbolAddress((void**)&aQ,  hA_Q);
    cudaGetSymbolAddress((void**)&aPP, hA_P);
    cudaGetSymbolAddress((void**)&aAOp,hA_AOp);
    cudaGetSymbolAddress((void**)&aAOe,hA_AOe);
    cudaGetSymbolAddress((void**)&bQP, hB_qkvp);
    cudaGetSymbolAddress((void**)&bQE, hB_qkve);
    cudaGetSymbolAddress((void**)&bK,  hB_K);
    cudaGetSymbolAddress((void**)&bV,  hB_V);
    cudaGetSymbolAddress((void**)&bWP, hB_wop);
    cudaGetSymbolAddress((void**)&bWE, hB_woe);

    // --- pack inputs ---
    launch_pack<true >(pali,   aP, LP, DP, DP, 1, 1, (long long)LP * DP, 0, 1, Bb);
    launch_pack<true >(expert, aE, LE, DE, DE, 1, 1, (long long)LE * DE, 0, 1, Bb);
    // fused QKV weights, transposed reads: rows n of [NQKV][Kaug]
    launch_pack<false>(wq_p, bQP,                    HH, DP, 1, HH, 1, 0, 0, 0, 1);
    launch_pack<false>(wk_p, bQP + (long long)HH * 2 * DP,        HD, DP, 1, HD, 1, 0, 0, 0, 1);
    launch_pack<false>(wv_p, bQP + (long long)(HH + HD) * 2 * DP, HD, DP, 1, HD, 1, 0, 0, 0, 1);
    launch_pack<false>(wq_e, bQE,                    HH, DE, 1, HH, 1, 0, 0, 0, 1);
    launch_pack<false>(wk_e, bQE + (long long)HH * 2 * DE,        HD, DE, 1, HD, 1, 0, 0, 0, 1);
    launch_pack<false>(wv_e, bQE + (long long)(HH + HD) * 2 * DE, HD, DE, 1, HD, 1, 0, 0, 0, 1);
    launch_pack<false>(wo_p, bWP, DP, HH, 1, DP, 1, 0, 0, 0, 1);
    launch_pack<false>(wo_e, bWE, DE, HH, 1, DE, 1, 0, 0, 0, 1);

    // --- QKV projections -> g_QKV [b][row][2560] ---
    launch_gemm(aP, bQP, QKV, nullptr, NQKV / 128, LP / 128, Bb, 2 * DP,
                (long long)LP * 2 * DP, 0, 31, (long long)Lt * NQKV, 0, 0, NQKV, 1.f, 0, 0);
    launch_gemm(aE, bQE, QKV + (long long)LP * NQKV, nullptr, NQKV / 128, LE / 128, Bb, 2 * DE,
                (long long)LE * 2 * DE, 0, 31, (long long)Lt * NQKV, 0, 0, NQKV, 1.f, 0, 0);

    // --- RoPE ---
    rope_kernel<<<Bb * Lt, 128>>>(QKV, pos);

    // --- pack Q (per b,h), K (per b), V^T (per b) ---
    launch_pack<true >(QKV,        aQ, Lt, HD, NQKV, 1, 8, (long long)Lt * NQKV, HD, 1, Bb * Hh);
    launch_pack<true >(QKV + HH,   bK, Lt, HD, NQKV, 1, 1, (long long)Lt * NQKV, 0, 0, Bb);
    launch_pack<false>(QKV + HH + HD, bV, HD, Lt, 1, NQKV, 1, (long long)Lt * NQKV, 0, 0, Bb);

    // --- scores = scale*QK^T + mask ---
    launch_gemm(aQ, bK, S, mask, Lt / 128, Lt / 128, Bb * Hh, 2 * HD,
                (long long)Lt * 2 * HD, (long long)Lt * 2 * HD, 3,
                (long long)Lt * Lt, 0, 0, Lt, 0.0625f, 1, (long long)Lt * Lt);

    // --- softmax + pack P ---
    softmax_pack<<<Bb * Hh * Lt, 128>>>(S, aPP);

    // --- AO = P @ V ---
    launch_gemm(aPP, bV, AO, nullptr, HD / 128, Lt / 128, Bb * Hh, 2 * Lt,
                (long long)Lt * 2 * Lt, (long long)HD * 2 * Lt, 3,
                (long long)Lt * HH, HD, 3, HH, 1.f, 0, 0);

    // --- pack AO, output projections ---
    launch_pack<true >(AO,                      aAOp, LP, HH, HH, 1, 1, (long long)Lt * HH, 0, 1, Bb);
    launch_pack<true >(AO + (long long)LP * HH, aAOe, LE, HH, HH, 1, 1, (long long)Lt * HH, 0, 1, Bb);
    launch_gemm(aAOp, bWP, out, nullptr, DP / 128, LP / 128, Bb, 2 * HH,
                (long long)LP * 2 * HH, 0, 31, (long long)LP * DP, 0, 0, DP, 1.f, 0, 0);
    launch_gemm(aAOe, bWE, out + (long long)Bb * LP * DP, nullptr, DE / 128, LE / 128, Bb, 2 * HH,
                (long long)LE * 2 * HH, 0, 31, (long long)LE * DE, 0, 0, DE, 1.f, 0, 0);
}

// round 6
// speedup vs baseline: 6.1449x; 1.1883x over previous
#include <cuda_runtime.h>
#include <cuda_fp16.h>
#include <math.h>
#include <stdint.h>

constexpr int Bb = 4, LP = 768, LE = 256, Lt = 1024;
constexpr int DP = 2048, DE = 1024, Hh = 8, HD = 256, HH = 2048;
constexpr int NQKV = HH + 2 * HD;  // 2560

// fp32 scratch
__device__ __align__(1024) float g_QKV[(size_t)Bb * Lt * NQKV];
__device__ __align__(1024) float g_S[(size_t)Bb * Hh * Lt * Lt];

// packed fp16 operands, K-major rows [R][2K] (hi | lo-or-hi)
__device__ __align__(1024) __half hA_pali[(size_t)Bb * LP * 4096];
__device__ __align__(1024) __half hA_exp [(size_t)Bb * LE * 2048];
__device__ __align__(1024) __half hA_Q   [(size_t)Bb * Hh * Lt * 512];
__device__ __align__(1024) __half hA_P   [(size_t)Bb * Hh * Lt * 2048];
__device__ __align__(1024) __half hAO    [(size_t)Bb * Lt * 4096];
__device__ __align__(1024) __half hB_qkvp[(size_t)NQKV * 4096];
__device__ __align__(1024) __half hB_qkve[(size_t)NQKV * 2048];
__device__ __align__(1024) __half hB_K   [(size_t)Bb * Lt * 512];
__device__ __align__(1024) __half hB_V   [(size_t)Bb * HD * 2048];
__device__ __align__(1024) __half hB_wop [(size_t)DP * 4096];
__device__ __align__(1024) __half hB_woe [(size_t)DE * 4096];

__device__ __forceinline__ uint32_t s2u(const void* p) {
    uint32_t a;
    asm("{ .reg .u64 t; cvta.to.shared.u64 t, %1; cvt.u32.u64 %0, t; }" : "=r"(a) : "l"(p));
    return a;
}

#define CP_ASYNC16(saddr, gaddr) \
    asm volatile("cp.async.cg.shared.global [%0], [%1], 16;" :: "r"(saddr), "l"(gaddr))
#define CP_COMMIT() asm volatile("cp.async.commit_group;")
#define CP_WAIT(n)  asm volatile("cp.async.wait_group %0;" :: "n"(n))

#define LDSM4(r, addr)                                                       \
    asm volatile("ldmatrix.sync.aligned.m8n8.x4.shared.b16 {%0,%1,%2,%3}, [%4];" \
        : "=r"((r)[0]), "=r"((r)[1]), "=r"((r)[2]), "=r"((r)[3]) : "r"(addr))

#define MMA16816(c, a, b0, b1)                                               \
    asm volatile("mma.sync.aligned.m16n8k16.row.col.f32.f16.f16.f32 "        \
        "{%0,%1,%2,%3},{%4,%5,%6,%7},{%8,%9},{%0,%1,%2,%3};"                 \
        : "+f"((c)[0]), "+f"((c)[1]), "+f"((c)[2]), "+f"((c)[3])             \
        : "r"((a)[0]), "r"((a)[1]), "r"((a)[2]), "r"((a)[3]), "r"(b0), "r"(b1))

// ---------------------------------------------------------------------------
// HMMA GEMM (TN): 128x128 tile, BK=64, 256 thr (8 warps of 32x64),
// double-buffered cp.async, XOR-swizzled smem.
// Epilogues: fp32 (+ optional scale+mask) or packed fp16 hi|lo (out_half).
// ---------------------------------------------------------------------------
constexpr int GEMM_SMEM = 65536;

__global__ void __launch_bounds__(256, 2) gemm_hmma(
    const __half* __restrict__ Ap, const __half* __restrict__ Bp,
    float* __restrict__ C, const float* __restrict__ mask,
    int Kaug, long long sAz, long long sBz, int zshB,
    long long cso, long long csi, int czsh, int ldc,
    float scale, int use_mask, long long mzs, int out_half)
{
    extern __shared__ __align__(1024) char smem[];
    const uint32_t sbase = s2u(smem);
    const int t = threadIdx.x;
    const int z = blockIdx.z;

    const __half* Ag = Ap + (long long)z * sAz + (long long)blockIdx.y * 128 * Kaug;
    const __half* Bg = Bp + (long long)(z >> zshB) * sBz + (long long)blockIdx.x * 128 * Kaug;

    const int lrow = t >> 3, lc = t & 7;

    float acc[2][8][4];
#pragma unroll
    for (int i = 0; i < 2; i++)
#pragma unroll
        for (int j = 0; j < 8; j++)
#pragma unroll
            for (int k = 0; k < 4; k++) acc[i][j][k] = 0.f;

    const int nch = Kaug >> 6;

#define STAGE(s, k0) do {                                                    \
    uint32_t _sA = sbase + (s) * 32768;                                      \
    uint32_t _sB = _sA + 16384;                                              \
    _Pragma("unroll")                                                        \
    for (int _i = 0; _i < 4; _i++) {                                         \
        int _r = lrow + _i * 32;                                             \
        uint32_t _sw = ((uint32_t)(lc ^ (_r & 7))) << 4;                     \
        CP_ASYNC16(_sA + _r * 128 + _sw, Ag + (long long)_r * Kaug + (k0) + lc * 8); \
        CP_ASYNC16(_sB + _r * 128 + _sw, Bg + (long long)_r * Kaug + (k0) + lc * 8); \
    }                                                                        \
    CP_COMMIT();                                                             \
} while (0)

    STAGE(0, 0);

    const int wid = t >> 5, lane = t & 31;
    const int wm = wid >> 1, wn = wid & 1;
    const int a_r = lane & 15, a_c = lane >> 4;
    const int b_r = (lane & 7) + ((lane >> 4) << 3), b_c = (lane >> 3) & 1;

    for (int ch = 0; ch < nch; ch++) {
        if (ch + 1 < nch) { STAGE((ch + 1) & 1, (ch + 1) << 6); CP_WAIT(1); }
        else              { CP_WAIT(0); }
        __syncthreads();
        uint32_t sA = sbase + (ch & 1) * 32768;
        uint32_t sB = sA + 16384;
#pragma unroll
        for (int ks = 0; ks < 4; ks++) {
            const int kc = ks << 1;
            uint32_t a[2][4];
#pragma unroll
            for (int mt = 0; mt < 2; mt++) {
                int r = wm * 32 + mt * 16 + a_r;
                LDSM4(a[mt], sA + r * 128 + ((uint32_t)((kc + a_c) ^ (r & 7)) << 4));
            }
            uint32_t b[4][4];
#pragma unroll
            for (int nt2 = 0; nt2 < 4; nt2++) {
                int n = wn * 64 + nt2 * 16 + b_r;
                LDSM4(b[nt2], sB + n * 128 + ((uint32_t)((kc + b_c) ^ (n & 7)) << 4));
            }
#pragma unroll
            for (int mt = 0; mt < 2; mt++)
#pragma unroll
                for (int nt = 0; nt < 8; nt++)
                    MMA16816(acc[mt][nt], a[mt], b[nt >> 1][(nt & 1) * 2], b[nt >> 1][(nt & 1) * 2 + 1]);
        }
        __syncthreads();
    }

    const long long coff = ((long long)(z >> czsh)) * cso +
                           (long long)(z & ((1 << czsh) - 1)) * csi;
    const int g = lane >> 2, tig = lane & 3;
#pragma unroll
    for (int mt = 0; mt < 2; mt++) {
#pragma unroll
        for (int h2 = 0; h2 < 2; h2++) {
            long long row = (long long)blockIdx.y * 128 + wm * 32 + mt * 16 + g + h2 * 8;
            long long cb = row * (long long)ldc + (long long)blockIdx.x * 128 + wn * 64 + tig * 2;
            if (out_half) {
                __half* crow = reinterpret_cast<__half*>(C) + coff + cb;
#pragma unroll
                for (int nt = 0; nt < 8; nt++) {
                    float v0 = acc[mt][nt][h2 * 2 + 0];
                    float v1 = acc[mt][nt][h2 * 2 + 1];
                    __half h0 = __float2half_rn(v0), h1 = __float2half_rn(v1);
                    __half l0 = __float2half_rn(v0 - __half2float(h0));
                    __half l1 = __float2half_rn(v1 - __half2float(h1));
                    *reinterpret_cast<__half2*>(crow + nt * 8)        = __halves2half2(h0, h1);
                    *reinterpret_cast<__half2*>(crow + 2048 + nt * 8) = __halves2half2(l0, l1);
                }
            } else {
                float* crow = C + coff + cb;
                const float* mrow = use_mask ? (mask + (long long)(z >> 3) * mzs + cb) : nullptr;
#pragma unroll
                for (int nt = 0; nt < 8; nt++) {
                    float v0 = acc[mt][nt][h2 * 2 + 0];
                    float v1 = acc[mt][nt][h2 * 2 + 1];
                    if (use_mask) { v0 = v0 * scale + mrow[nt * 8]; v1 = v1 * scale + mrow[nt * 8 + 1]; }
                    *reinterpret_cast<float2*>(crow + nt * 8) = make_float2(v0, v1);
                }
            }
        }
    }
#undef STAGE
}

// ---------------------------------------------------------------------------
// Megapack: embeds (direct, hi|lo) + weights (smem transpose, hi|hi dup)
// ---------------------------------------------------------------------------
struct Seg {
    const float* src; __half* dst;
    int nblocks; int mode; int aside; int R; int K;  // trans: R=N(dst rows), K=red dim
};
struct SegTable { Seg s[10]; };

__global__ void __launch_bounds__(256) megapack(SegTable st)
{
    __shared__ float sm[32][33];
    int b = blockIdx.x, si = 0;
    while (b >= st.s[si].nblocks) { b -= st.s[si].nblocks; si++; }
    const Seg sg = st.s[si];

    if (sg.mode == 0) {
        long long idx = (long long)b * 256 + threadIdx.x;
        int K8 = sg.K >> 3;
        long long items = (long long)sg.R * K8;
        if (idx >= items) return;
        int kc = (int)(idx % K8);
        long long r = idx / K8;
        const float* sp = sg.src + r * (long long)sg.K + kc * 8;
        float4 x = *reinterpret_cast<const float4*>(sp);
        float4 y = *reinterpret_cast<const float4*>(sp + 4);
        float v[8] = {x.x, x.y, x.z, x.w, y.x, y.y, y.z, y.w};
        unsigned short hi[8], p1[8];
#pragma unroll
        for (int i = 0; i < 8; i++) {
            __half h = __float2half_rn(v[i]);
            hi[i] = __half_as_ushort(h);
            p1[i] = sg.aside ? __half_as_ushort(__float2half_rn(v[i] - __half2float(h))) : hi[i];
        }
        uint4 w0, w1;
        w0.x = hi[0] | ((uint32_t)hi[1] << 16); w0.y = hi[2] | ((uint32_t)hi[3] << 16);
        w0.z = hi[4] | ((uint32_t)hi[5] << 16); w0.w = hi[6] | ((uint32_t)hi[7] << 16);
        w1.x = p1[0] | ((uint32_t)p1[1] << 16); w1.y = p1[2] | ((uint32_t)p1[3] << 16);
        w1.z = p1[4] | ((uint32_t)p1[5] << 16); w1.w = p1[6] | ((uint32_t)p1[7] << 16);
        __half* dp = sg.dst + r * (2LL * sg.K) + kc * 8;
        *reinterpret_cast<uint4*>(dp)        = w0;
        *reinterpret_cast<uint4*>(dp + sg.K) = w1;
    } else {
        int nx = sg.K >> 5;
        int k0 = (b % nx) * 32, n0 = (b / nx) * 32;
        int tx = threadIdx.x & 31, ty = threadIdx.x >> 5;  // ty 0..7
#pragma unroll
        for (int i = 0; i < 4; i++)
            sm[ty + 8 * i][tx] = sg.src[(long long)(k0 + ty + 8 * i) * sg.R + n0 + tx];
        __syncthreads();
#pragma unroll
        for (int i = 0; i < 4; i++) {
            int n = n0 + ty + 8 * i;
            __half h = __float2half_rn(sm[tx][ty + 8 * i]);
            __half* d = sg.dst + (long long)n * (2LL * sg.K) + k0 + tx;
            d[0]    = h;
            d[sg.K] = h;
        }
    }
}

// ---------------------------------------------------------------------------
// Fused RoPE + pack of Q (hi|lo, per b,h) and K (hi|hi, per b)
// ---------------------------------------------------------------------------
__global__ void __launch_bounds__(128) qkrope_pack(
    const float* __restrict__ QKV, const int* __restrict__ pos,
    __half* __restrict__ aQ, __half* __restrict__ bK)
{
    const int bl = blockIdx.x;
    const int bidx = bl >> 10, l = bl & 1023;
    const int i = threadIdx.x;
    const float p = (float)pos[bl];
    const float inv = powf(10000.0f, -(float)i * (1.0f / 128.0f));
    float s, c;
    sincosf(p * inv, &s, &c);

    const float* row = QKV + (long long)bl * NQKV;
#pragma unroll
    for (int h = 0; h < Hh; h++) {
        float x1 = row[h * HD + i], x2 = row[h * HD + 128 + i];
        float r1 = x1 * c - x2 * s, r2 = x2 * c + x1 * s;
        __half h1 = __float2half_rn(r1), h2 = __float2half_rn(r2);
        __half l1 = __float2half_rn(r1 - __half2float(h1));
        __half l2 = __float2half_rn(r2 - __half2float(h2));
        __half* q = aQ + (((long long)(bidx * Hh + h) * Lt + l) * 512);
        q[i] = h1; q[128 + i] = h2; q[256 + i] = l1; q[384 + i] = l2;
    }
    float x1 = row[HH + i], x2 = row[HH + 128 + i];
    float r1 = x1 * c - x2 * s, r2 = x2 * c + x1 * s;
    __half h1 = __float2half_rn(r1), h2 = __float2half_rn(r2);
    __half* kd = bK + ((long long)bidx * Lt + l) * 512;
    kd[i] = h1; kd[128 + i] = h2; kd[256 + i] = h1; kd[384 + i] = h2;
}

// ---------------------------------------------------------------------------
// V transpose-pack: bV[b][d][2*Lt] = hi|hi of QKV[b][l][HH+HD+d]
// ---------------------------------------------------------------------------
__global__ void __launch_bounds__(256) vtpack(const float* __restrict__ QKV,
                                              __half* __restrict__ bV)
{
    __shared__ float sm[32][33];
    const int bidx = blockIdx.z;
    const int l0 = blockIdx.x * 32, d0 = blockIdx.y * 32;
    const int tx = threadIdx.x & 31, ty = threadIdx.x >> 5;
#pragma unroll
    for (int i = 0; i < 4; i++)
        sm[ty + 8 * i][tx] = QKV[((long long)bidx * Lt + l0 + ty + 8 * i) * NQKV + HH + HD + d0 + tx];
    __syncthreads();
#pragma unroll
    for (int i = 0; i < 4; i++) {
        int d = d0 + ty + 8 * i;
        __half h = __float2half_rn(sm[tx][ty + 8 * i]);
        __half* dp = bV + ((long long)bidx * HD + d) * 2048 + l0 + tx;
        dp[0]    = h;
        dp[1024] = h;
    }
}

// ---------------------------------------------------------------------------
// Softmax over S rows (len 1024) + packed fp16 P (hi|lo)
// ---------------------------------------------------------------------------
__global__ void __launch_bounds__(128) softmax_pack(const float* __restrict__ S,
                                                    __half* __restrict__ P)
{
    __shared__ float red[128];
    const long long rowid = blockIdx.x;
    const float* p = S + rowid * Lt;
    const int t = threadIdx.x, k0 = t * 8;

    float v[8];
    float4 a = *reinterpret_cast<const float4*>(p + k0);
    float4 b = *reinterpret_cast<const float4*>(p + k0 + 4);
    v[0]=a.x; v[1]=a.y; v[2]=a.z; v[3]=a.w; v[4]=b.x; v[5]=b.y; v[6]=b.z; v[7]=b.w;

    float m = v[0];
#pragma unroll
    for (int i = 1; i < 8; i++) m = fmaxf(m, v[i]);
    red[t] = m; __syncthreads();
    for (int s = 64; s > 0; s >>= 1) { if (t < s) red[t] = fmaxf(red[t], red[t + s]); __syncthreads(); }
    m = red[0]; __syncthreads();

    float sum = 0.f;
#pragma unroll
    for (int i = 0; i < 8; i++) { v[i] = expf(v[i] - m); sum += v[i]; }
    red[t] = sum; __syncthreads();
    for (int s = 64; s > 0; s >>= 1) { if (t < s) red[t] += red[t + s]; __syncthreads(); }
    const float invs = 1.0f / red[0];

    unsigned short hi[8], lo[8];
#pragma unroll
    for (int i = 0; i < 8; i++) {
        float x = v[i] * invs;
        __half h = __float2half_rn(x);
        __half l = __float2half_rn(x - __half2float(h));
        hi[i] = __half_as_ushort(h);
        lo[i] = __half_as_ushort(l);
    }
    uint4 whi, wlo;
    whi.x = hi[0] | ((uint32_t)hi[1] << 16); whi.y = hi[2] | ((uint32_t)hi[3] << 16);
    whi.z = hi[4] | ((uint32_t)hi[5] << 16); whi.w = hi[6] | ((uint32_t)hi[7] << 16);
    wlo.x = lo[0] | ((uint32_t)lo[1] << 16); wlo.y = lo[2] | ((uint32_t)lo[3] << 16);
    wlo.z = lo[4] | ((uint32_t)lo[5] << 16); wlo.w = lo[6] | ((uint32_t)lo[7] << 16);

    __half* base = P + rowid * 2048 + k0;
    *reinterpret_cast<uint4*>(base)        = whi;
    *reinterpret_cast<uint4*>(base + 1024) = wlo;
}

// ---------------------------------------------------------------------------
// Host
// ---------------------------------------------------------------------------
static void launch_gemm(const __half* A, const __half* B, void* C, const float* mask,
                        int nt, int mt, int Z, int Kaug, long long sAz, long long sBz,
                        int zshB, long long cso, long long csi, int czsh, int ldc,
                        float scale, int use_mask, long long mzs, int out_half)
{
    dim3 grid(nt, mt, Z);
    gemm_hmma<<<grid, 256, GEMM_SMEM>>>(A, B, (float*)C, mask, Kaug, sAz, sBz, zshB,
                                        cso, csi, czsh, ldc, scale, use_mask, mzs, out_half);
}

extern "C" void kernel_launch(void* const* d_in, const int* in_sizes, int n_in,
                              void* d_out, int out_size)
{
    const float* pali   = (const float*)d_in[0];
    const float* expert = (const float*)d_in[1];
    const int*   pos    = (const int*)d_in[2];
    const float* mask   = (const float*)d_in[3];
    const float* wq_p = (const float*)d_in[5];
    const float* wk_p = (const float*)d_in[6];
    const float* wv_p = (const float*)d_in[7];
    const float* wo_p = (const float*)d_in[8];
    const float* wq_e = (const float*)d_in[9];
    const float* wk_e = (const float*)d_in[10];
    const float* wv_e = (const float*)d_in[11];
    const float* wo_e = (const float*)d_in[12];
    float* out = (float*)d_out;

    cudaFuncSetAttribute(gemm_hmma, cudaFuncAttributeMaxDynamicSharedMemorySize, GEMM_SMEM);

    float *QKV, *S;
    cudaGetSymbolAddress((void**)&QKV, g_QKV);
    cudaGetSymbolAddress((void**)&S,   g_S);
    __half *aP, *aE, *aQ, *aPP, *AO, *bQP, *bQE, *bK, *bV, *bWP, *bWE;
    cudaGetSymbolAddress((void**)&aP,  hA_pali);
    cudaGetSymbolAddress((void**)&aE,  hA_exp);
    cudaGetSymbolAddress((void**)&aQ,  hA_Q);
    cudaGetSymbolAddress((void**)&aPP, hA_P);
    cudaGetSymbolAddress((void**)&AO,  hAO);
    cudaGetSymbolAddress((void**)&bQP, hB_qkvp);
    cudaGetSymbolAddress((void**)&bQE, hB_qkve);
    cudaGetSymbolAddress((void**)&bK,  hB_K);
    cudaGetSymbolAddress((void**)&bV,  hB_V);
    cudaGetSymbolAddress((void**)&bWP, hB_wop);
    cudaGetSymbolAddress((void**)&bWE, hB_woe);

    // --- megapack: embeds direct + weights transposed ---
    SegTable st;
    int nb = 0;
    auto setd = [&](int i, const float* s, __half* d, int R, int K, int aside) {
        st.s[i] = {s, d, (int)(((long long)R * K / 8 + 255) / 256), 0, aside, R, K};
        nb += st.s[i].nblocks;
    };
    auto sett = [&](int i, const float* s, __half* d, int N, int K) {
        st.s[i] = {s, d, (K / 32) * (N / 32), 1, 0, N, K};
        nb += st.s[i].nblocks;
    };
    setd(0, pali,   aP, Bb * LP, DP, 1);
    setd(1, expert, aE, Bb * LE, DE, 1);
    sett(2, wq_p, bQP,                          HH, DP);
    sett(3, wk_p, bQP + (long long)HH * 2 * DP,        HD, DP);
    sett(4, wv_p, bQP + (long long)(HH + HD) * 2 * DP, HD, DP);
    sett(5, wq_e, bQE,                          HH, DE);
    sett(6, wk_e, bQE + (long long)HH * 2 * DE,        HD, DE);
    sett(7, wv_e, bQE + (long long)(HH + HD) * 2 * DE, HD, DE);
    sett(8, wo_p, bWP, DP, HH);
    sett(9, wo_e, bWE, DE, HH);
    megapack<<<nb, 256>>>(st);

    // --- QKV projections -> g_QKV [b][row][2560] ---
    launch_gemm(aP, bQP, QKV, nullptr, NQKV / 128, LP / 128, Bb, 2 * DP,
                (long long)LP * 2 * DP, 0, 31, (long long)Lt * NQKV, 0, 0, NQKV, 1.f, 0, 0, 0);
    launch_gemm(aE, bQE, QKV + (long long)LP * NQKV, nullptr, NQKV / 128, LE / 128, Bb, 2 * DE,
                (long long)LE * 2 * DE, 0, 31, (long long)Lt * NQKV, 0, 0, NQKV, 1.f, 0, 0, 0);

    // --- V transpose-pack, then fused RoPE + Q/K pack ---
    {
        dim3 g(Lt / 32, HD / 32, Bb);
        vtpack<<<g, 256>>>(QKV, bV);
    }
    qkrope_pack<<<Bb * Lt, 128>>>(QKV, pos, aQ, bK);

    // --- scores = scale*QK^T + mask ---  (launch #6: profiled by ncu)
    launch_gemm(aQ, bK, S, mask, Lt / 128, Lt / 128, Bb * Hh, 512,
                (long long)Lt * 512, (long long)Lt * 512, 3,
                (long long)Lt * Lt, 0, 0, Lt, 0.0625f, 1, (long long)Lt * Lt, 0);

    // --- softmax + pack P ---
    softmax_pack<<<Bb * Hh * Lt, 128>>>(S, aPP);

    // --- AO = P @ V, epilogue writes packed fp16 hi|lo directly ---
    launch_gemm(aPP, bV, AO, nullptr, HD / 128, Lt / 128, Bb * Hh, 2 * Lt,
                (long long)Lt * 2 * Lt, (long long)HD * 2 * Lt, 3,
                (long long)Lt * 4096, HD, 3, 4096, 1.f, 0, 0, 1);

    // --- output projections ---
    launch_gemm(AO, bWP, out, nullptr, DP / 128, LP / 128, Bb, 2 * HH,
                (long long)Lt * 4096, 0, 31, (long long)LP * DP, 0, 0, DP, 1.f, 0, 0, 0);
    launch_gemm(AO + (long long)LP * 4096, bWE, out + (long long)Bb * LP * DP, nullptr,
                DE / 128, LE / 128, Bb, 2 * HH,
                (long long)Lt * 4096, 0, 31, (long long)LE * DE, 0, 0, DE, 1.f, 0, 0, 0);
}

// round 7
// speedup vs baseline: 6.2378x; 1.0151x over previous
#include <cuda_runtime.h>
#include <cuda_fp16.h>
#include <math.h>
#include <stdint.h>

constexpr int Bb = 4, LP = 768, LE = 256, Lt = 1024;
constexpr int DP = 2048, DE = 1024, Hh = 8, HD = 256, HH = 2048;
constexpr int NQKV = HH + 2 * HD;  // 2560

// fp32 scratch
__device__ __align__(1024) float g_QKV[(size_t)Bb * Lt * NQKV];
__device__ __align__(1024) float g_S[(size_t)Bb * Hh * Lt * Lt];

// packed fp16 operands, K-major rows [R][2K] (hi | lo-or-hi)
__device__ __align__(1024) __half hA_pali[(size_t)Bb * LP * 4096];
__device__ __align__(1024) __half hA_exp [(size_t)Bb * LE * 2048];
__device__ __align__(1024) __half hA_Q   [(size_t)Bb * Hh * Lt * 512];
__device__ __align__(1024) __half hA_P   [(size_t)Bb * Hh * Lt * 2048];
__device__ __align__(1024) __half hAO    [(size_t)Bb * Lt * 4096];
__device__ __align__(1024) __half hB_qkvp[(size_t)NQKV * 4096];
__device__ __align__(1024) __half hB_qkve[(size_t)NQKV * 2048];
__device__ __align__(1024) __half hB_K   [(size_t)Bb * Lt * 512];
__device__ __align__(1024) __half hB_V   [(size_t)Bb * HD * 2048];
__device__ __align__(1024) __half hB_wop [(size_t)DP * 4096];
__device__ __align__(1024) __half hB_woe [(size_t)DE * 4096];

__device__ __forceinline__ uint32_t s2u(const void* p) {
    uint32_t a;
    asm("{ .reg .u64 t; cvta.to.shared.u64 t, %1; cvt.u32.u64 %0, t; }" : "=r"(a) : "l"(p));
    return a;
}

#define CP_ASYNC16(saddr, gaddr) \
    asm volatile("cp.async.cg.shared.global [%0], [%1], 16;" :: "r"(saddr), "l"(gaddr))
#define CP_COMMIT() asm volatile("cp.async.commit_group;")
#define CP_WAIT(n)  asm volatile("cp.async.wait_group %0;" :: "n"(n))

#define LDSM4(r, addr)                                                       \
    asm volatile("ldmatrix.sync.aligned.m8n8.x4.shared.b16 {%0,%1,%2,%3}, [%4];" \
        : "=r"((r)[0]), "=r"((r)[1]), "=r"((r)[2]), "=r"((r)[3]) : "r"(addr))

#define MMA16816(c, a, b0, b1)                                               \
    asm volatile("mma.sync.aligned.m16n8k16.row.col.f32.f16.f16.f32 "        \
        "{%0,%1,%2,%3},{%4,%5,%6,%7},{%8,%9},{%0,%1,%2,%3};"                 \
        : "+f"((c)[0]), "+f"((c)[1]), "+f"((c)[2]), "+f"((c)[3])             \
        : "r"((a)[0]), "r"((a)[1]), "r"((a)[2]), "r"((a)[3]), "r"(b0), "r"(b1))

// ---------------------------------------------------------------------------
// HMMA GEMM (TN): 128x128 tile, BK=64, 256 thr (8 warps of 32x64).
// 3-stage cp.async ring (one __syncthreads per chunk) + register fragment
// double-buffering across k16 steps. XOR-swizzled smem.
// Epilogues: fp32 (+ optional scale+mask) or packed fp16 hi|lo (out_half).
// ---------------------------------------------------------------------------
constexpr int GEMM_SMEM = 98304;  // 3 stages x (16KB A + 16KB B)

__global__ void __launch_bounds__(256, 2) gemm_hmma(
    const __half* __restrict__ Ap, const __half* __restrict__ Bp,
    float* __restrict__ C, const float* __restrict__ mask,
    int Kaug, long long sAz, long long sBz, int zshB,
    long long cso, long long csi, int czsh, int ldc,
    float scale, int use_mask, long long mzs, int out_half)
{
    extern __shared__ __align__(1024) char smem[];
    const uint32_t sbase = s2u(smem);
    const int t = threadIdx.x;
    const int z = blockIdx.z;

    const __half* Ag = Ap + (long long)z * sAz + (long long)blockIdx.y * 128 * Kaug;
    const __half* Bg = Bp + (long long)(z >> zshB) * sBz + (long long)blockIdx.x * 128 * Kaug;

    const int lrow = t >> 3, lc = t & 7;

    float acc[2][8][4];
#pragma unroll
    for (int i = 0; i < 2; i++)
#pragma unroll
        for (int j = 0; j < 8; j++)
#pragma unroll
            for (int k = 0; k < 4; k++) acc[i][j][k] = 0.f;

    const int nch = Kaug >> 6;

#define STAGE(s, k0) do {                                                    \
    uint32_t _sA = sbase + (s) * 32768;                                      \
    uint32_t _sB = _sA + 16384;                                              \
    _Pragma("unroll")                                                        \
    for (int _i = 0; _i < 4; _i++) {                                         \
        int _r = lrow + _i * 32;                                             \
        uint32_t _sw = ((uint32_t)(lc ^ (_r & 7))) << 4;                     \
        CP_ASYNC16(_sA + _r * 128 + _sw, Ag + (long long)_r * Kaug + (k0) + lc * 8); \
        CP_ASYNC16(_sB + _r * 128 + _sw, Bg + (long long)_r * Kaug + (k0) + lc * 8); \
    }                                                                        \
    CP_COMMIT();                                                             \
} while (0)

    STAGE(0, 0);
    if (nch > 1) STAGE(1, 64);

    const int wid = t >> 5, lane = t & 31;
    const int wm = wid >> 1, wn = wid & 1;
    const int a_r = lane & 15, a_c = lane >> 4;
    const int b_r = (lane & 7) + ((lane >> 4) << 3), b_c = (lane >> 3) & 1;

    int slot = 0, slot2 = (nch > 2) ? 2 : 0;  // slot of chunk ch, and of ch+2

    for (int ch = 0; ch < nch; ch++) {
        if (ch + 1 < nch) CP_WAIT(1); else CP_WAIT(0);
        __syncthreads();
        if (ch + 2 < nch) {
            STAGE(slot2, (ch + 2) << 6);
            slot2 = (slot2 == 2) ? 0 : slot2 + 1;
        }
        uint32_t sA = sbase + slot * 32768;
        uint32_t sB = sA + 16384;
        slot = (slot == 2) ? 0 : slot + 1;

        uint32_t a[2][2][4], b[2][4][4];
        // prefetch ks=0 fragments
        {
            const int kc = 0;
#pragma unroll
            for (int mt = 0; mt < 2; mt++) {
                int r = wm * 32 + mt * 16 + a_r;
                LDSM4(a[0][mt], sA + r * 128 + ((uint32_t)((kc + a_c) ^ (r & 7)) << 4));
            }
#pragma unroll
            for (int nt2 = 0; nt2 < 4; nt2++) {
                int n = wn * 64 + nt2 * 16 + b_r;
                LDSM4(b[0][nt2], sB + n * 128 + ((uint32_t)((kc + b_c) ^ (n & 7)) << 4));
            }
        }
#pragma unroll
        for (int ks = 0; ks < 4; ks++) {
            const int cur = ks & 1, nxt = cur ^ 1;
            if (ks < 3) {
                const int kc = (ks + 1) << 1;
#pragma unroll
                for (int mt = 0; mt < 2; mt++) {
                    int r = wm * 32 + mt * 16 + a_r;
                    LDSM4(a[nxt][mt], sA + r * 128 + ((uint32_t)((kc + a_c) ^ (r & 7)) << 4));
                }
#pragma unroll
                for (int nt2 = 0; nt2 < 4; nt2++) {
                    int n = wn * 64 + nt2 * 16 + b_r;
                    LDSM4(b[nxt][nt2], sB + n * 128 + ((uint32_t)((kc + b_c) ^ (n & 7)) << 4));
                }
            }
#pragma unroll
            for (int mt = 0; mt < 2; mt++)
#pragma unroll
                for (int nt = 0; nt < 8; nt++)
                    MMA16816(acc[mt][nt], a[cur][mt],
                             b[cur][nt >> 1][(nt & 1) * 2], b[cur][nt >> 1][(nt & 1) * 2 + 1]);
        }
    }

    const long long coff = ((long long)(z >> czsh)) * cso +
                           (long long)(z & ((1 << czsh) - 1)) * csi;
    const int g = lane >> 2, tig = lane & 3;
#pragma unroll
    for (int mt = 0; mt < 2; mt++) {
#pragma unroll
        for (int h2 = 0; h2 < 2; h2++) {
            long long row = (long long)blockIdx.y * 128 + wm * 32 + mt * 16 + g + h2 * 8;
            long long cb = row * (long long)ldc + (long long)blockIdx.x * 128 + wn * 64 + tig * 2;
            if (out_half) {
                __half* crow = reinterpret_cast<__half*>(C) + coff + cb;
#pragma unroll
                for (int nt = 0; nt < 8; nt++) {
                    float v0 = acc[mt][nt][h2 * 2 + 0];
                    float v1 = acc[mt][nt][h2 * 2 + 1];
                    __half h0 = __float2half_rn(v0), h1 = __float2half_rn(v1);
                    __half l0 = __float2half_rn(v0 - __half2float(h0));
                    __half l1 = __float2half_rn(v1 - __half2float(h1));
                    *reinterpret_cast<__half2*>(crow + nt * 8)        = __halves2half2(h0, h1);
                    *reinterpret_cast<__half2*>(crow + 2048 + nt * 8) = __halves2half2(l0, l1);
                }
            } else {
                float* crow = C + coff + cb;
                const float* mrow = use_mask ? (mask + (long long)(z >> 3) * mzs + cb) : nullptr;
#pragma unroll
                for (int nt = 0; nt < 8; nt++) {
                    float v0 = acc[mt][nt][h2 * 2 + 0];
                    float v1 = acc[mt][nt][h2 * 2 + 1];
                    if (use_mask) { v0 = v0 * scale + mrow[nt * 8]; v1 = v1 * scale + mrow[nt * 8 + 1]; }
                    *reinterpret_cast<float2*>(crow + nt * 8) = make_float2(v0, v1);
                }
            }
        }
    }
#undef STAGE
}

// ---------------------------------------------------------------------------
// Megapack: embeds (direct, hi|lo) + weights (smem transpose, hi|hi dup)
// ---------------------------------------------------------------------------
struct Seg {
    const float* src; __half* dst;
    int nblocks; int mode; int aside; int R; int K;
};
struct SegTable { Seg s[10]; };

__global__ void __launch_bounds__(256) megapack(SegTable st)
{
    __shared__ float sm[32][33];
    int b = blockIdx.x, si = 0;
    while (b >= st.s[si].nblocks) { b -= st.s[si].nblocks; si++; }
    const Seg sg = st.s[si];

    if (sg.mode == 0) {
        long long idx = (long long)b * 256 + threadIdx.x;
        int K8 = sg.K >> 3;
        long long items = (long long)sg.R * K8;
        if (idx >= items) return;
        int kc = (int)(idx % K8);
        long long r = idx / K8;
        const float* sp = sg.src + r * (long long)sg.K + kc * 8;
        float4 x = *reinterpret_cast<const float4*>(sp);
        float4 y = *reinterpret_cast<const float4*>(sp + 4);
        float v[8] = {x.x, x.y, x.z, x.w, y.x, y.y, y.z, y.w};
        unsigned short hi[8], p1[8];
#pragma unroll
        for (int i = 0; i < 8; i++) {
            __half h = __float2half_rn(v[i]);
            hi[i] = __half_as_ushort(h);
            p1[i] = sg.aside ? __half_as_ushort(__float2half_rn(v[i] - __half2float(h))) : hi[i];
        }
        uint4 w0, w1;
        w0.x = hi[0] | ((uint32_t)hi[1] << 16); w0.y = hi[2] | ((uint32_t)hi[3] << 16);
        w0.z = hi[4] | ((uint32_t)hi[5] << 16); w0.w = hi[6] | ((uint32_t)hi[7] << 16);
        w1.x = p1[0] | ((uint32_t)p1[1] << 16); w1.y = p1[2] | ((uint32_t)p1[3] << 16);
        w1.z = p1[4] | ((uint32_t)p1[5] << 16); w1.w = p1[6] | ((uint32_t)p1[7] << 16);
        __half* dp = sg.dst + r * (2LL * sg.K) + kc * 8;
        *reinterpret_cast<uint4*>(dp)        = w0;
        *reinterpret_cast<uint4*>(dp + sg.K) = w1;
    } else {
        int nx = sg.K >> 5;
        int k0 = (b % nx) * 32, n0 = (b / nx) * 32;
        int tx = threadIdx.x & 31, ty = threadIdx.x >> 5;
#pragma unroll
        for (int i = 0; i < 4; i++)
            sm[ty + 8 * i][tx] = sg.src[(long long)(k0 + ty + 8 * i) * sg.R + n0 + tx];
        __syncthreads();
#pragma unroll
        for (int i = 0; i < 4; i++) {
            int n = n0 + ty + 8 * i;
            __half h = __float2half_rn(sm[tx][ty + 8 * i]);
            __half* d = sg.dst + (long long)n * (2LL * sg.K) + k0 + tx;
            d[0]    = h;
            d[sg.K] = h;
        }
    }
}

// ---------------------------------------------------------------------------
// Fused RoPE + pack of Q (hi|lo, per b,h) and K (hi|hi, per b)
// ---------------------------------------------------------------------------
__global__ void __launch_bounds__(128) qkrope_pack(
    const float* __restrict__ QKV, const int* __restrict__ pos,
    __half* __restrict__ aQ, __half* __restrict__ bK)
{
    const int bl = blockIdx.x;
    const int bidx = bl >> 10, l = bl & 1023;
    const int i = threadIdx.x;
    const float p = (float)pos[bl];
    const float inv = powf(10000.0f, -(float)i * (1.0f / 128.0f));
    float s, c;
    sincosf(p * inv, &s, &c);

    const float* row = QKV + (long long)bl * NQKV;
#pragma unroll
    for (int h = 0; h < Hh; h++) {
        float x1 = row[h * HD + i], x2 = row[h * HD + 128 + i];
        float r1 = x1 * c - x2 * s, r2 = x2 * c + x1 * s;
        __half h1 = __float2half_rn(r1), h2 = __float2half_rn(r2);
        __half l1 = __float2half_rn(r1 - __half2float(h1));
        __half l2 = __float2half_rn(r2 - __half2float(h2));
        __half* q = aQ + (((long long)(bidx * Hh + h) * Lt + l) * 512);
        q[i] = h1; q[128 + i] = h2; q[256 + i] = l1; q[384 + i] = l2;
    }
    float x1 = row[HH + i], x2 = row[HH + 128 + i];
    float r1 = x1 * c - x2 * s, r2 = x2 * c + x1 * s;
    __half h1 = __float2half_rn(r1), h2 = __float2half_rn(r2);
    __half* kd = bK + ((long long)bidx * Lt + l) * 512;
    kd[i] = h1; kd[128 + i] = h2; kd[256 + i] = h1; kd[384 + i] = h2;
}

// ---------------------------------------------------------------------------
// V transpose-pack: bV[b][d][2*Lt] = hi|hi of QKV[b][l][HH+HD+d]
// ---------------------------------------------------------------------------
__global__ void __launch_bounds__(256) vtpack(const float* __restrict__ QKV,
                                              __half* __restrict__ bV)
{
    __shared__ float sm[32][33];
    const int bidx = blockIdx.z;
    const int l0 = blockIdx.x * 32, d0 = blockIdx.y * 32;
    const int tx = threadIdx.x & 31, ty = threadIdx.x >> 5;
#pragma unroll
    for (int i = 0; i < 4; i++)
        sm[ty + 8 * i][tx] = QKV[((long long)bidx * Lt + l0 + ty + 8 * i) * NQKV + HH + HD + d0 + tx];
    __syncthreads();
#pragma unroll
    for (int i = 0; i < 4; i++) {
        int d = d0 + ty + 8 * i;
        __half h = __float2half_rn(sm[tx][ty + 8 * i]);
        __half* dp = bV + ((long long)bidx * HD + d) * 2048 + l0 + tx;
        dp[0]    = h;
        dp[1024] = h;
    }
}

// ---------------------------------------------------------------------------
// Softmax over S rows (len 1024) + packed fp16 P (hi|lo)
// ---------------------------------------------------------------------------
__global__ void __launch_bounds__(128) softmax_pack(const float* __restrict__ S,
                                                    __half* __restrict__ P)
{
    __shared__ float red[128];
    const long long rowid = blockIdx.x;
    const float* p = S + rowid * Lt;
    const int t = threadIdx.x, k0 = t * 8;

    float v[8];
    float4 a = *reinterpret_cast<const float4*>(p + k0);
    float4 b = *reinterpret_cast<const float4*>(p + k0 + 4);
    v[0]=a.x; v[1]=a.y; v[2]=a.z; v[3]=a.w; v[4]=b.x; v[5]=b.y; v[6]=b.z; v[7]=b.w;

    float m = v[0];
#pragma unroll
    for (int i = 1; i < 8; i++) m = fmaxf(m, v[i]);
    red[t] = m; __syncthreads();
    for (int s = 64; s > 0; s >>= 1) { if (t < s) red[t] = fmaxf(red[t], red[t + s]); __syncthreads(); }
    m = red[0]; __syncthreads();

    float sum = 0.f;
#pragma unroll
    for (int i = 0; i < 8; i++) { v[i] = expf(v[i] - m); sum += v[i]; }
    red[t] = sum; __syncthreads();
    for (int s = 64; s > 0; s >>= 1) { if (t < s) red[t] += red[t + s]; __syncthreads(); }
    const float invs = 1.0f / red[0];

    unsigned short hi[8], lo[8];
#pragma unroll
    for (int i = 0; i < 8; i++) {
        float x = v[i] * invs;
        __half h = __float2half_rn(x);
        __half l = __float2half_rn(x - __half2float(h));
        hi[i] = __half_as_ushort(h);
        lo[i] = __half_as_ushort(l);
    }
    uint4 whi, wlo;
    whi.x = hi[0] | ((uint32_t)hi[1] << 16); whi.y = hi[2] | ((uint32_t)hi[3] << 16);
    whi.z = hi[4] | ((uint32_t)hi[5] << 16); whi.w = hi[6] | ((uint32_t)hi[7] << 16);
    wlo.x = lo[0] | ((uint32_t)lo[1] << 16); wlo.y = lo[2] | ((uint32_t)lo[3] << 16);
    wlo.z = lo[4] | ((uint32_t)lo[5] << 16); wlo.w = lo[6] | ((uint32_t)lo[7] << 16);

    __half* base = P + rowid * 2048 + k0;
    *reinterpret_cast<uint4*>(base)        = whi;
    *reinterpret_cast<uint4*>(base + 1024) = wlo;
}

// ---------------------------------------------------------------------------
// Host
// ---------------------------------------------------------------------------
static void launch_gemm(const __half* A, const __half* B, void* C, const float* mask,
                        int nt, int mt, int Z, int Kaug, long long sAz, long long sBz,
                        int zshB, long long cso, long long csi, int czsh, int ldc,
                        float scale, int use_mask, long long mzs, int out_half)
{
    dim3 grid(nt, mt, Z);
    gemm_hmma<<<grid, 256, GEMM_SMEM>>>(A, B, (float*)C, mask, Kaug, sAz, sBz, zshB,
                                        cso, csi, czsh, ldc, scale, use_mask, mzs, out_half);
}

extern "C" void kernel_launch(void* const* d_in, const int* in_sizes, int n_in,
                              void* d_out, int out_size)
{
    const float* pali   = (const float*)d_in[0];
    const float* expert = (const float*)d_in[1];
    const int*   pos    = (const int*)d_in[2];
    const float* mask   = (const float*)d_in[3];
    const float* wq_p = (const float*)d_in[5];
    const float* wk_p = (const float*)d_in[6];
    const float* wv_p = (const float*)d_in[7];
    const float* wo_p = (const float*)d_in[8];
    const float* wq_e = (const float*)d_in[9];
    const float* wk_e = (const float*)d_in[10];
    const float* wv_e = (const float*)d_in[11];
    const float* wo_e = (const float*)d_in[12];
    float* out = (float*)d_out;

    cudaFuncSetAttribute(gemm_hmma, cudaFuncAttributeMaxDynamicSharedMemorySize, GEMM_SMEM);

    float *QKV, *S;
    cudaGetSymbolAddress((void**)&QKV, g_QKV);
    cudaGetSymbolAddress((void**)&S,   g_S);
    __half *aP, *aE, *aQ, *aPP, *AO, *bQP, *bQE, *bK, *bV, *bWP, *bWE;
    cudaGetSymbolAddress((void**)&aP,  hA_pali);
    cudaGetSymbolAddress((void**)&aE,  hA_exp);
    cudaGetSymbolAddress((void**)&aQ,  hA_Q);
    cudaGetSymbolAddress((void**)&aPP, hA_P);
    cudaGetSymbolAddress((void**)&AO,  hAO);
    cudaGetSymbolAddress((void**)&bQP, hB_qkvp);
    cudaGetSymbolAddress((void**)&bQE, hB_qkve);
    cudaGetSymbolAddress((void**)&bK,  hB_K);
    cudaGetSymbolAddress((void**)&bV,  hB_V);
    cudaGetSymbolAddress((void**)&bWP, hB_wop);
    cudaGetSymbolAddress((void**)&bWE, hB_woe);

    SegTable st;
    int nb = 0;
    auto setd = [&](int i, const float* s, __half* d, int R, int K, int aside) {
        st.s[i] = {s, d, (int)(((long long)R * K / 8 + 255) / 256), 0, aside, R, K};
        nb += st.s[i].nblocks;
    };
    auto sett = [&](int i, const float* s, __half* d, int N, int K) {
        st.s[i] = {s, d, (K / 32) * (N / 32), 1, 0, N, K};
        nb += st.s[i].nblocks;
    };
    setd(0, pali,   aP, Bb * LP, DP, 1);
    setd(1, expert, aE, Bb * LE, DE, 1);
    sett(2, wq_p, bQP,                          HH, DP);
    sett(3, wk_p, bQP + (long long)HH * 2 * DP,        HD, DP);
    sett(4, wv_p, bQP + (long long)(HH + HD) * 2 * DP, HD, DP);
    sett(5, wq_e, bQE,                          HH, DE);
    sett(6, wk_e, bQE + (long long)HH * 2 * DE,        HD, DE);
    sett(7, wv_e, bQE + (long long)(HH + HD) * 2 * DE, HD, DE);
    sett(8, wo_p, bWP, DP, HH);
    sett(9, wo_e, bWE, DE, HH);
    megapack<<<nb, 256>>>(st);

    // --- QKV projections -> g_QKV [b][row][2560] ---
    launch_gemm(aP, bQP, QKV, nullptr, NQKV / 128, LP / 128, Bb, 2 * DP,
                (long long)LP * 2 * DP, 0, 31, (long long)Lt * NQKV, 0, 0, NQKV, 1.f, 0, 0, 0);
    launch_gemm(aE, bQE, QKV + (long long)LP * NQKV, nullptr, NQKV / 128, LE / 128, Bb, 2 * DE,
                (long long)LE * 2 * DE, 0, 31, (long long)Lt * NQKV, 0, 0, NQKV, 1.f, 0, 0, 0);

    // --- V transpose-pack, then fused RoPE + Q/K pack ---
    {
        dim3 g(Lt / 32, HD / 32, Bb);
        vtpack<<<g, 256>>>(QKV, bV);
    }
    qkrope_pack<<<Bb * Lt, 128>>>(QKV, pos, aQ, bK);

    // --- scores = scale*QK^T + mask ---
    launch_gemm(aQ, bK, S, mask, Lt / 128, Lt / 128, Bb * Hh, 512,
                (long long)Lt * 512, (long long)Lt * 512, 3,
                (long long)Lt * Lt, 0, 0, Lt, 0.0625f, 1, (long long)Lt * Lt, 0);

    // --- softmax + pack P ---
    softmax_pack<<<Bb * Hh * Lt, 128>>>(S, aPP);

    // --- AO = P @ V, epilogue writes packed fp16 hi|lo directly ---
    launch_gemm(aPP, bV, AO, nullptr, HD / 128, Lt / 128, Bb * Hh, 2 * Lt,
                (long long)Lt * 2 * Lt, (long long)HD * 2 * Lt, 3,
                (long long)Lt * 4096, HD, 3, 4096, 1.f, 0, 0, 1);

    // --- output projections ---
    launch_gemm(AO, bWP, out, nullptr, DP / 128, LP / 128, Bb, 2 * HH,
                (long long)Lt * 4096, 0, 31, (long long)LP * DP, 0, 0, DP, 1.f, 0, 0, 0);
    launch_gemm(AO + (long long)LP * 4096, bWE, out + (long long)Bb * LP * DP, nullptr,
                DE / 128, LE / 128, Bb, 2 * HH,
                (long long)Lt * 4096, 0, 31, (long long)LE * DE, 0, 0, DE, 1.f, 0, 0, 0);
}

// round 8
// speedup vs baseline: 10.2915x; 1.6499x over previous
#include <cuda_runtime.h>
#include <cuda_fp16.h>
#include <math.h>
#include <stdint.h>

constexpr int Bb = 4, LP = 768, LE = 256, Lt = 1024;
constexpr int DP = 2048, DE = 1024, Hh = 8, HD = 256, HH = 2048;
constexpr int NQKV = HH + 2 * HD;  // 2560

// fp32 scratch
__device__ __align__(1024) float g_QKV[(size_t)Bb * Lt * NQKV];
__device__ __align__(1024) float g_S[(size_t)Bb * Hh * Lt * Lt];

// packed fp16 operands, K-major rows [R][K]
__device__ __align__(1024) __half hA_pali[(size_t)Bb * LP * DP];
__device__ __align__(1024) __half hA_exp [(size_t)Bb * LE * DE];
__device__ __align__(1024) __half hA_Q   [(size_t)Bb * Hh * Lt * HD];
__device__ __align__(1024) __half hA_P   [(size_t)Bb * Hh * Lt * Lt];
__device__ __align__(1024) __half hAO    [(size_t)Bb * Lt * HH];
__device__ __align__(1024) __half hB_qkvp[(size_t)NQKV * DP];
__device__ __align__(1024) __half hB_qkve[(size_t)NQKV * DE];
__device__ __align__(1024) __half hB_K   [(size_t)Bb * Lt * HD];
__device__ __align__(1024) __half hB_V   [(size_t)Bb * HD * Lt];
__device__ __align__(1024) __half hB_wop [(size_t)DP * HH];
__device__ __align__(1024) __half hB_woe [(size_t)DE * HH];

__device__ __forceinline__ uint32_t s2u(const void* p) {
    uint32_t a;
    asm("{ .reg .u64 t; cvta.to.shared.u64 t, %1; cvt.u32.u64 %0, t; }" : "=r"(a) : "l"(p));
    return a;
}

#define CP_ASYNC16(saddr, gaddr) \
    asm volatile("cp.async.cg.shared.global [%0], [%1], 16;" :: "r"(saddr), "l"(gaddr))
#define CP_COMMIT() asm volatile("cp.async.commit_group;")
#define CP_WAIT(n)  asm volatile("cp.async.wait_group %0;" :: "n"(n))

#define LDSM4(r, addr)                                                       \
    asm volatile("ldmatrix.sync.aligned.m8n8.x4.shared.b16 {%0,%1,%2,%3}, [%4];" \
        : "=r"((r)[0]), "=r"((r)[1]), "=r"((r)[2]), "=r"((r)[3]) : "r"(addr))

#define MMA16816(c, a, b0, b1)                                               \
    asm volatile("mma.sync.aligned.m16n8k16.row.col.f32.f16.f16.f32 "        \
        "{%0,%1,%2,%3},{%4,%5,%6,%7},{%8,%9},{%0,%1,%2,%3};"                 \
        : "+f"((c)[0]), "+f"((c)[1]), "+f"((c)[2]), "+f"((c)[3])             \
        : "r"((a)[0]), "r"((a)[1]), "r"((a)[2]), "r"((a)[3]), "r"(b0), "r"(b1))

// ---------------------------------------------------------------------------
// HMMA GEMM (TN): 128x128 tile, BK=64, 256 thr (8 warps of 32x64).
// 3-stage cp.async ring + register fragment double-buffering. XOR swizzle.
// Epilogues: fp32 (+ optional scale+mask) or fp16 (out_half).
// ---------------------------------------------------------------------------
constexpr int GEMM_SMEM = 98304;

__global__ void __launch_bounds__(256, 2) gemm_hmma(
    const __half* __restrict__ Ap, const __half* __restrict__ Bp,
    float* __restrict__ C, const float* __restrict__ mask,
    int K, long long sAz, long long sBz, int zshB,
    long long cso, long long csi, int czsh, int ldc,
    float scale, int use_mask, long long mzs, int out_half)
{
    extern __shared__ __align__(1024) char smem[];
    const uint32_t sbase = s2u(smem);
    const int t = threadIdx.x;
    const int z = blockIdx.z;

    const __half* Ag = Ap + (long long)z * sAz + (long long)blockIdx.y * 128 * K;
    const __half* Bg = Bp + (long long)(z >> zshB) * sBz + (long long)blockIdx.x * 128 * K;

    const int lrow = t >> 3, lc = t & 7;

    float acc[2][8][4];
#pragma unroll
    for (int i = 0; i < 2; i++)
#pragma unroll
        for (int j = 0; j < 8; j++)
#pragma unroll
            for (int k = 0; k < 4; k++) acc[i][j][k] = 0.f;

    const int nch = K >> 6;

#define STAGE(s, k0) do {                                                    \
    uint32_t _sA = sbase + (s) * 32768;                                      \
    uint32_t _sB = _sA + 16384;                                              \
    _Pragma("unroll")                                                        \
    for (int _i = 0; _i < 4; _i++) {                                         \
        int _r = lrow + _i * 32;                                             \
        uint32_t _sw = ((uint32_t)(lc ^ (_r & 7))) << 4;                     \
        CP_ASYNC16(_sA + _r * 128 + _sw, Ag + (long long)_r * K + (k0) + lc * 8); \
        CP_ASYNC16(_sB + _r * 128 + _sw, Bg + (long long)_r * K + (k0) + lc * 8); \
    }                                                                        \
    CP_COMMIT();                                                             \
} while (0)

    STAGE(0, 0);
    if (nch > 1) STAGE(1, 64);

    const int wid = t >> 5, lane = t & 31;
    const int wm = wid >> 1, wn = wid & 1;
    const int a_r = lane & 15, a_c = lane >> 4;
    const int b_r = (lane & 7) + ((lane >> 4) << 3), b_c = (lane >> 3) & 1;

    int slot = 0, slot2 = (nch > 2) ? 2 : 0;

    for (int ch = 0; ch < nch; ch++) {
        if (ch + 1 < nch) CP_WAIT(1); else CP_WAIT(0);
        __syncthreads();
        if (ch + 2 < nch) {
            STAGE(slot2, (ch + 2) << 6);
            slot2 = (slot2 == 2) ? 0 : slot2 + 1;
        }
        uint32_t sA = sbase + slot * 32768;
        uint32_t sB = sA + 16384;
        slot = (slot == 2) ? 0 : slot + 1;

        uint32_t a[2][2][4], b[2][4][4];
        {
            const int kc = 0;
#pragma unroll
            for (int mt = 0; mt < 2; mt++) {
                int r = wm * 32 + mt * 16 + a_r;
                LDSM4(a[0][mt], sA + r * 128 + ((uint32_t)((kc + a_c) ^ (r & 7)) << 4));
            }
#pragma unroll
            for (int nt2 = 0; nt2 < 4; nt2++) {
                int n = wn * 64 + nt2 * 16 + b_r;
                LDSM4(b[0][nt2], sB + n * 128 + ((uint32_t)((kc + b_c) ^ (n & 7)) << 4));
            }
        }
#pragma unroll
        for (int ks = 0; ks < 4; ks++) {
            const int cur = ks & 1, nxt = cur ^ 1;
            if (ks < 3) {
                const int kc = (ks + 1) << 1;
#pragma unroll
                for (int mt = 0; mt < 2; mt++) {
                    int r = wm * 32 + mt * 16 + a_r;
                    LDSM4(a[nxt][mt], sA + r * 128 + ((uint32_t)((kc + a_c) ^ (r & 7)) << 4));
                }
#pragma unroll
                for (int nt2 = 0; nt2 < 4; nt2++) {
                    int n = wn * 64 + nt2 * 16 + b_r;
                    LDSM4(b[nxt][nt2], sB + n * 128 + ((uint32_t)((kc + b_c) ^ (n & 7)) << 4));
                }
            }
#pragma unroll
            for (int mt = 0; mt < 2; mt++)
#pragma unroll
                for (int nt = 0; nt < 8; nt++)
                    MMA16816(acc[mt][nt], a[cur][mt],
                             b[cur][nt >> 1][(nt & 1) * 2], b[cur][nt >> 1][(nt & 1) * 2 + 1]);
        }
    }

    const long long coff = ((long long)(z >> czsh)) * cso +
                           (long long)(z & ((1 << czsh) - 1)) * csi;
    const int g = lane >> 2, tig = lane & 3;
#pragma unroll
    for (int mt = 0; mt < 2; mt++) {
#pragma unroll
        for (int h2 = 0; h2 < 2; h2++) {
            long long row = (long long)blockIdx.y * 128 + wm * 32 + mt * 16 + g + h2 * 8;
            long long cb = row * (long long)ldc + (long long)blockIdx.x * 128 + wn * 64 + tig * 2;
            if (out_half) {
                __half* crow = reinterpret_cast<__half*>(C) + coff + cb;
#pragma unroll
                for (int nt = 0; nt < 8; nt++) {
                    __half h0 = __float2half_rn(acc[mt][nt][h2 * 2 + 0]);
                    __half h1 = __float2half_rn(acc[mt][nt][h2 * 2 + 1]);
                    *reinterpret_cast<__half2*>(crow + nt * 8) = __halves2half2(h0, h1);
                }
            } else {
                float* crow = C + coff + cb;
                const float* mrow = use_mask ? (mask + (long long)(z >> 3) * mzs + cb) : nullptr;
#pragma unroll
                for (int nt = 0; nt < 8; nt++) {
                    float v0 = acc[mt][nt][h2 * 2 + 0];
                    float v1 = acc[mt][nt][h2 * 2 + 1];
                    if (use_mask) { v0 = v0 * scale + mrow[nt * 8]; v1 = v1 * scale + mrow[nt * 8 + 1]; }
                    *reinterpret_cast<float2*>(crow + nt * 8) = make_float2(v0, v1);
                }
            }
        }
    }
#undef STAGE
}

// ---------------------------------------------------------------------------
// Megapack: embeds (direct fp16) + weights (smem transpose fp16)
// ---------------------------------------------------------------------------
struct Seg {
    const float* src; __half* dst;
    int nblocks; int mode; int R; int K;
};
struct SegTable { Seg s[10]; };

__global__ void __launch_bounds__(256) megapack(SegTable st)
{
    __shared__ float sm[32][33];
    int b = blockIdx.x, si = 0;
    while (b >= st.s[si].nblocks) { b -= st.s[si].nblocks; si++; }
    const Seg sg = st.s[si];

    if (sg.mode == 0) {
        long long idx = (long long)b * 256 + threadIdx.x;
        int K8 = sg.K >> 3;
        long long items = (long long)sg.R * K8;
        if (idx >= items) return;
        int kc = (int)(idx % K8);
        long long r = idx / K8;
        const float* sp = sg.src + r * (long long)sg.K + kc * 8;
        float4 x = *reinterpret_cast<const float4*>(sp);
        float4 y = *reinterpret_cast<const float4*>(sp + 4);
        float v[8] = {x.x, x.y, x.z, x.w, y.x, y.y, y.z, y.w};
        unsigned short o[8];
#pragma unroll
        for (int i = 0; i < 8; i++) o[i] = __half_as_ushort(__float2half_rn(v[i]));
        uint4 w;
        w.x = o[0] | ((uint32_t)o[1] << 16); w.y = o[2] | ((uint32_t)o[3] << 16);
        w.z = o[4] | ((uint32_t)o[5] << 16); w.w = o[6] | ((uint32_t)o[7] << 16);
        *reinterpret_cast<uint4*>(sg.dst + r * (long long)sg.K + kc * 8) = w;
    } else {
        int nx = sg.K >> 5;
        int k0 = (b % nx) * 32, n0 = (b / nx) * 32;
        int tx = threadIdx.x & 31, ty = threadIdx.x >> 5;
#pragma unroll
        for (int i = 0; i < 4; i++)
            sm[ty + 8 * i][tx] = sg.src[(long long)(k0 + ty + 8 * i) * sg.R + n0 + tx];
        __syncthreads();
#pragma unroll
        for (int i = 0; i < 4; i++) {
            int n = n0 + ty + 8 * i;
            sg.dst[(long long)n * sg.K + k0 + tx] = __float2half_rn(sm[tx][ty + 8 * i]);
        }
    }
}

// ---------------------------------------------------------------------------
// Fused RoPE + fp16 pack of Q (per b,h) and K (per b)
// ---------------------------------------------------------------------------
__global__ void __launch_bounds__(128) qkrope_pack(
    const float* __restrict__ QKV, const int* __restrict__ pos,
    __half* __restrict__ aQ, __half* __restrict__ bK)
{
    const int bl = blockIdx.x;
    const int bidx = bl >> 10, l = bl & 1023;
    const int i = threadIdx.x;
    const float p = (float)pos[bl];
    const float inv = powf(10000.0f, -(float)i * (1.0f / 128.0f));
    float s, c;
    sincosf(p * inv, &s, &c);

    const float* row = QKV + (long long)bl * NQKV;
#pragma unroll
    for (int h = 0; h < Hh; h++) {
        float x1 = row[h * HD + i], x2 = row[h * HD + 128 + i];
        __half* q = aQ + (((long long)(bidx * Hh + h) * Lt + l) * HD);
        q[i]       = __float2half_rn(x1 * c - x2 * s);
        q[128 + i] = __float2half_rn(x2 * c + x1 * s);
    }
    float x1 = row[HH + i], x2 = row[HH + 128 + i];
    __half* kd = bK + ((long long)bidx * Lt + l) * HD;
    kd[i]       = __float2half_rn(x1 * c - x2 * s);
    kd[128 + i] = __float2half_rn(x2 * c + x1 * s);
}

// ---------------------------------------------------------------------------
// V transpose-pack: bV[b][d][Lt]
// ---------------------------------------------------------------------------
__global__ void __launch_bounds__(256) vtpack(const float* __restrict__ QKV,
                                              __half* __restrict__ bV)
{
    __shared__ float sm[32][33];
    const int bidx = blockIdx.z;
    const int l0 = blockIdx.x * 32, d0 = blockIdx.y * 32;
    const int tx = threadIdx.x & 31, ty = threadIdx.x >> 5;
#pragma unroll
    for (int i = 0; i < 4; i++)
        sm[ty + 8 * i][tx] = QKV[((long long)bidx * Lt + l0 + ty + 8 * i) * NQKV + HH + HD + d0 + tx];
    __syncthreads();
#pragma unroll
    for (int i = 0; i < 4; i++) {
        int d = d0 + ty + 8 * i;
        bV[((long long)bidx * HD + d) * Lt + l0 + tx] = __float2half_rn(sm[tx][ty + 8 * i]);
    }
}

// ---------------------------------------------------------------------------
// Softmax over S rows (len 1024) + fp16 P
// ---------------------------------------------------------------------------
__global__ void __launch_bounds__(128) softmax_pack(const float* __restrict__ S,
                                                    __half* __restrict__ P)
{
    __shared__ float red[128];
    const long long rowid = blockIdx.x;
    const float* p = S + rowid * Lt;
    const int t = threadIdx.x, k0 = t * 8;

    float v[8];
    float4 a = *reinterpret_cast<const float4*>(p + k0);
    float4 b = *reinterpret_cast<const float4*>(p + k0 + 4);
    v[0]=a.x; v[1]=a.y; v[2]=a.z; v[3]=a.w; v[4]=b.x; v[5]=b.y; v[6]=b.z; v[7]=b.w;

    float m = v[0];
#pragma unroll
    for (int i = 1; i < 8; i++) m = fmaxf(m, v[i]);
    red[t] = m; __syncthreads();
    for (int s = 64; s > 0; s >>= 1) { if (t < s) red[t] = fmaxf(red[t], red[t + s]); __syncthreads(); }
    m = red[0]; __syncthreads();

    float sum = 0.f;
#pragma unroll
    for (int i = 0; i < 8; i++) { v[i] = expf(v[i] - m); sum += v[i]; }
    red[t] = sum; __syncthreads();
    for (int s = 64; s > 0; s >>= 1) { if (t < s) red[t] += red[t + s]; __syncthreads(); }
    const float invs = 1.0f / red[0];

    unsigned short o[8];
#pragma unroll
    for (int i = 0; i < 8; i++) o[i] = __half_as_ushort(__float2half_rn(v[i] * invs));
    uint4 w;
    w.x = o[0] | ((uint32_t)o[1] << 16); w.y = o[2] | ((uint32_t)o[3] << 16);
    w.z = o[4] | ((uint32_t)o[5] << 16); w.w = o[6] | ((uint32_t)o[7] << 16);
    *reinterpret_cast<uint4*>(P + rowid * Lt + k0) = w;
}

// ---------------------------------------------------------------------------
// Host
// ---------------------------------------------------------------------------
static void launch_gemm(const __half* A, const __half* B, void* C, const float* mask,
                        int nt, int mt, int Z, int K, long long sAz, long long sBz,
                        int zshB, long long cso, long long csi, int czsh, int ldc,
                        float scale, int use_mask, long long mzs, int out_half)
{
    dim3 grid(nt, mt, Z);
    gemm_hmma<<<grid, 256, GEMM_SMEM>>>(A, B, (float*)C, mask, K, sAz, sBz, zshB,
                                        cso, csi, czsh, ldc, scale, use_mask, mzs, out_half);
}

extern "C" void kernel_launch(void* const* d_in, const int* in_sizes, int n_in,
                              void* d_out, int out_size)
{
    const float* pali   = (const float*)d_in[0];
    const float* expert = (const float*)d_in[1];
    const int*   pos    = (const int*)d_in[2];
    const float* mask   = (const float*)d_in[3];
    const float* wq_p = (const float*)d_in[5];
    const float* wk_p = (const float*)d_in[6];
    const float* wv_p = (const float*)d_in[7];
    const float* wo_p = (const float*)d_in[8];
    const float* wq_e = (const float*)d_in[9];
    const float* wk_e = (const float*)d_in[10];
    const float* wv_e = (const float*)d_in[11];
    const float* wo_e = (const float*)d_in[12];
    float* out = (float*)d_out;

    cudaFuncSetAttribute(gemm_hmma, cudaFuncAttributeMaxDynamicSharedMemorySize, GEMM_SMEM);

    float *QKV, *S;
    cudaGetSymbolAddress((void**)&QKV, g_QKV);
    cudaGetSymbolAddress((void**)&S,   g_S);
    __half *aP, *aE, *aQ, *aPP, *AO, *bQP, *bQE, *bK, *bV, *bWP, *bWE;
    cudaGetSymbolAddress((void**)&aP,  hA_pali);
    cudaGetSymbolAddress((void**)&aE,  hA_exp);
    cudaGetSymbolAddress((void**)&aQ,  hA_Q);
    cudaGetSymbolAddress((void**)&aPP, hA_P);
    cudaGetSymbolAddress((void**)&AO,  hAO);
    cudaGetSymbolAddress((void**)&bQP, hB_qkvp);
    cudaGetSymbolAddress((void**)&bQE, hB_qkve);
    cudaGetSymbolAddress((void**)&bK,  hB_K);
    cudaGetSymbolAddress((void**)&bV,  hB_V);
    cudaGetSymbolAddress((void**)&bWP, hB_wop);
    cudaGetSymbolAddress((void**)&bWE, hB_woe);

    SegTable st;
    int nb = 0;
    auto setd = [&](int i, const float* s, __half* d, int R, int K) {
        st.s[i] = {s, d, (int)(((long long)R * K / 8 + 255) / 256), 0, R, K};
        nb += st.s[i].nblocks;
    };
    auto sett = [&](int i, const float* s, __half* d, int N, int K) {
        st.s[i] = {s, d, (K / 32) * (N / 32), 1, N, K};
        nb += st.s[i].nblocks;
    };
    setd(0, pali,   aP, Bb * LP, DP);
    setd(1, expert, aE, Bb * LE, DE);
    sett(2, wq_p, bQP,                      HH, DP);
    sett(3, wk_p, bQP + (long long)HH * DP,        HD, DP);
    sett(4, wv_p, bQP + (long long)(HH + HD) * DP, HD, DP);
    sett(5, wq_e, bQE,                      HH, DE);
    sett(6, wk_e, bQE + (long long)HH * DE,        HD, DE);
    sett(7, wv_e, bQE + (long long)(HH + HD) * DE, HD, DE);
    sett(8, wo_p, bWP, DP, HH);
    sett(9, wo_e, bWE, DE, HH);
    megapack<<<nb, 256>>>(st);

    // --- QKV projections -> g_QKV [b][row][2560] ---
    launch_gemm(aP, bQP, QKV, nullptr, NQKV / 128, LP / 128, Bb, DP,
                (long long)LP * DP, 0, 31, (long long)Lt * NQKV, 0, 0, NQKV, 1.f, 0, 0, 0);
    launch_gemm(aE, bQE, QKV + (long long)LP * NQKV, nullptr, NQKV / 128, LE / 128, Bb, DE,
                (long long)LE * DE, 0, 31, (long long)Lt * NQKV, 0, 0, NQKV, 1.f, 0, 0, 0);

    // --- V transpose-pack, fused RoPE + Q/K pack ---
    {
        dim3 g(Lt / 32, HD / 32, Bb);
        vtpack<<<g, 256>>>(QKV, bV);
    }
    qkrope_pack<<<Bb * Lt, 128>>>(QKV, pos, aQ, bK);

    // --- scores = scale*QK^T + mask ---
    launch_gemm(aQ, bK, S, mask, Lt / 128, Lt / 128, Bb * Hh, HD,
                (long long)Lt * HD, (long long)Lt * HD, 3,
                (long long)Lt * Lt, 0, 0, Lt, 0.0625f, 1, (long long)Lt * Lt, 0);

    // --- softmax -> fp16 P ---
    softmax_pack<<<Bb * Hh * Lt, 128>>>(S, aPP);

    // --- AO = P @ V (fp16 out) ---
    launch_gemm(aPP, bV, AO, nullptr, HD / 128, Lt / 128, Bb * Hh, Lt,
                (long long)Lt * Lt, (long long)HD * Lt, 3,
                (long long)Lt * HH, HD, 3, HH, 1.f, 0, 0, 1);

    // --- output projections ---
    launch_gemm(AO, bWP, out, nullptr, DP / 128, LP / 128, Bb, HH,
                (long long)Lt * HH, 0, 31, (long long)LP * DP, 0, 0, DP, 1.f, 0, 0, 0);
    launch_gemm(AO + (long long)LP * HH, bWE, out + (long long)Bb * LP * DP, nullptr,
                DE / 128, LE / 128, Bb, HH,
                (long long)Lt * HH, 0, 31, (long long)LE * DE, 0, 0, DE, 1.f, 0, 0, 0);
}

// round 9
// speedup vs baseline: 10.4688x; 1.0172x over previous
#include <cuda_runtime.h>
#include <cuda_fp16.h>
#include <math.h>
#include <stdint.h>

constexpr int Bb = 4, LP = 768, LE = 256, Lt = 1024;
constexpr int DP = 2048, DE = 1024, Hh = 8, HD = 256, HH = 2048;
constexpr int NQKV = HH + 2 * HD;  // 2560

// fp32 scratch
__device__ __align__(1024) float g_QKV[(size_t)Bb * Lt * NQKV];
__device__ __align__(1024) float g_S[(size_t)Bb * Hh * Lt * Lt];

// packed fp16 operands, K-major rows [R][K]
__device__ __align__(1024) __half hA_pali[(size_t)Bb * LP * DP];
__device__ __align__(1024) __half hA_exp [(size_t)Bb * LE * DE];
__device__ __align__(1024) __half hA_Q   [(size_t)Bb * Hh * Lt * HD];
__device__ __align__(1024) __half hA_P   [(size_t)Bb * Hh * Lt * Lt];
__device__ __align__(1024) __half hAO    [(size_t)Bb * Lt * HH];
__device__ __align__(1024) __half hB_qkvp[(size_t)NQKV * DP];
__device__ __align__(1024) __half hB_qkve[(size_t)NQKV * DE];
__device__ __align__(1024) __half hB_K   [(size_t)Bb * Lt * HD];
__device__ __align__(1024) __half hB_V   [(size_t)Bb * HD * Lt];
__device__ __align__(1024) __half hB_wop [(size_t)DP * HH];
__device__ __align__(1024) __half hB_woe [(size_t)DE * HH];

__device__ __forceinline__ uint32_t s2u(const void* p) {
    uint32_t a;
    asm("{ .reg .u64 t; cvta.to.shared.u64 t, %1; cvt.u32.u64 %0, t; }" : "=r"(a) : "l"(p));
    return a;
}

#define CP_ASYNC16(saddr, gaddr) \
    asm volatile("cp.async.cg.shared.global [%0], [%1], 16;" :: "r"(saddr), "l"(gaddr))
#define CP_COMMIT() asm volatile("cp.async.commit_group;")
#define CP_WAIT(n)  asm volatile("cp.async.wait_group %0;" :: "n"(n))

#define LDSM4(r, addr)                                                       \
    asm volatile("ldmatrix.sync.aligned.m8n8.x4.shared.b16 {%0,%1,%2,%3}, [%4];" \
        : "=r"((r)[0]), "=r"((r)[1]), "=r"((r)[2]), "=r"((r)[3]) : "r"(addr))

#define MMA16816(c, a, b0, b1)                                               \
    asm volatile("mma.sync.aligned.m16n8k16.row.col.f32.f16.f16.f32 "        \
        "{%0,%1,%2,%3},{%4,%5,%6,%7},{%8,%9},{%0,%1,%2,%3};"                 \
        : "+f"((c)[0]), "+f"((c)[1]), "+f"((c)[2]), "+f"((c)[3])             \
        : "r"((a)[0]), "r"((a)[1]), "r"((a)[2]), "r"((a)[3]), "r"(b0), "r"(b1))

// ---------------------------------------------------------------------------
// Persistent multi-zone HMMA GEMM (TN): 128x128 tiles, BK=64, 8 warps,
// 3-stage cp.async ring, fragment double-buffering, XOR swizzle.
// Grid-strides over a flattened tile list spanning up to 2 independent GEMMs.
// ---------------------------------------------------------------------------
constexpr int GEMM_SMEM = 98304;

struct GZone {
    const __half* A; const __half* B; float* C; const float* mask;
    long long sAz, sBz, cso, csi, mzs;
    int K, zshB, czsh, ldc, use_mask, out_half, nt, mt, tstart;
    float scale;
};
struct GZones { GZone z[2]; int nz; int total; };

__global__ void __launch_bounds__(256, 2) gemm_hmma(GZones gz)
{
    extern __shared__ __align__(1024) char smem[];
    const uint32_t sbase = s2u(smem);
    const int t = threadIdx.x;
    const int lrow = t >> 3, lc = t & 7;
    const int wid = t >> 5, lane = t & 31;
    const int wm = wid >> 1, wn = wid & 1;
    const int a_r = lane & 15, a_c = lane >> 4;
    const int b_r = (lane & 7) + ((lane >> 4) << 3), b_c = (lane >> 3) & 1;

    for (int tix = blockIdx.x; tix < gz.total; tix += gridDim.x) {
        const int zi = (gz.nz > 1 && tix >= gz.z[1].tstart) ? 1 : 0;
        const GZone& d = gz.z[zi];
        const int lt2 = tix - d.tstart;
        const int bx = lt2 % d.nt;
        const int tmp = lt2 / d.nt;
        const int by = tmp % d.mt, bz = tmp / d.mt;
        const int K = d.K;
        const int nch = K >> 6;

        const __half* Ag = d.A + (long long)bz * d.sAz + (long long)by * 128 * K;
        const __half* Bg = d.B + (long long)(bz >> d.zshB) * d.sBz + (long long)bx * 128 * K;

        float acc[2][8][4];
#pragma unroll
        for (int i = 0; i < 2; i++)
#pragma unroll
            for (int j = 0; j < 8; j++)
#pragma unroll
                for (int k = 0; k < 4; k++) acc[i][j][k] = 0.f;

#define STAGE(s, k0) do {                                                    \
    uint32_t _sA = sbase + (s) * 32768;                                      \
    uint32_t _sB = _sA + 16384;                                              \
    _Pragma("unroll")                                                        \
    for (int _i = 0; _i < 4; _i++) {                                         \
        int _r = lrow + _i * 32;                                             \
        uint32_t _sw = ((uint32_t)(lc ^ (_r & 7))) << 4;                     \
        CP_ASYNC16(_sA + _r * 128 + _sw, Ag + (long long)_r * K + (k0) + lc * 8); \
        CP_ASYNC16(_sB + _r * 128 + _sw, Bg + (long long)_r * K + (k0) + lc * 8); \
    }                                                                        \
    CP_COMMIT();                                                             \
} while (0)

        __syncthreads();  // smem ring reuse across tiles
        STAGE(0, 0);
        if (nch > 1) STAGE(1, 64);

        int slot = 0, slot2 = (nch > 2) ? 2 : 0;
        for (int ch = 0; ch < nch; ch++) {
            if (ch + 1 < nch) CP_WAIT(1); else CP_WAIT(0);
            __syncthreads();
            if (ch + 2 < nch) {
                STAGE(slot2, (ch + 2) << 6);
                slot2 = (slot2 == 2) ? 0 : slot2 + 1;
            }
            uint32_t sA = sbase + slot * 32768;
            uint32_t sB = sA + 16384;
            slot = (slot == 2) ? 0 : slot + 1;

            uint32_t a[2][2][4], b[2][4][4];
            {
#pragma unroll
                for (int mt2 = 0; mt2 < 2; mt2++) {
                    int r = wm * 32 + mt2 * 16 + a_r;
                    LDSM4(a[0][mt2], sA + r * 128 + ((uint32_t)(a_c ^ (r & 7)) << 4));
                }
#pragma unroll
                for (int nt2 = 0; nt2 < 4; nt2++) {
                    int n = wn * 64 + nt2 * 16 + b_r;
                    LDSM4(b[0][nt2], sB + n * 128 + ((uint32_t)(b_c ^ (n & 7)) << 4));
                }
            }
#pragma unroll
            for (int ks = 0; ks < 4; ks++) {
                const int cur = ks & 1, nxt = cur ^ 1;
                if (ks < 3) {
                    const int kc = (ks + 1) << 1;
#pragma unroll
                    for (int mt2 = 0; mt2 < 2; mt2++) {
                        int r = wm * 32 + mt2 * 16 + a_r;
                        LDSM4(a[nxt][mt2], sA + r * 128 + ((uint32_t)((kc + a_c) ^ (r & 7)) << 4));
                    }
#pragma unroll
                    for (int nt2 = 0; nt2 < 4; nt2++) {
                        int n = wn * 64 + nt2 * 16 + b_r;
                        LDSM4(b[nxt][nt2], sB + n * 128 + ((uint32_t)((kc + b_c) ^ (n & 7)) << 4));
                    }
                }
#pragma unroll
                for (int mt2 = 0; mt2 < 2; mt2++)
#pragma unroll
                    for (int nt = 0; nt < 8; nt++)
                        MMA16816(acc[mt2][nt], a[cur][mt2],
                                 b[cur][nt >> 1][(nt & 1) * 2], b[cur][nt >> 1][(nt & 1) * 2 + 1]);
            }
        }
#undef STAGE

        const long long coff = ((long long)(bz >> d.czsh)) * d.cso +
                               (long long)(bz & ((1 << d.czsh) - 1)) * d.csi;
        const int g = lane >> 2, tig = lane & 3;
#pragma unroll
        for (int mt2 = 0; mt2 < 2; mt2++) {
#pragma unroll
            for (int h2 = 0; h2 < 2; h2++) {
                long long row = (long long)by * 128 + wm * 32 + mt2 * 16 + g + h2 * 8;
                long long cb = row * (long long)d.ldc + (long long)bx * 128 + wn * 64 + tig * 2;
                if (d.out_half) {
                    __half* crow = reinterpret_cast<__half*>(d.C) + coff + cb;
#pragma unroll
                    for (int nt = 0; nt < 8; nt++) {
                        __half h0 = __float2half_rn(acc[mt2][nt][h2 * 2 + 0]);
                        __half h1 = __float2half_rn(acc[mt2][nt][h2 * 2 + 1]);
                        *reinterpret_cast<__half2*>(crow + nt * 8) = __halves2half2(h0, h1);
                    }
                } else {
                    float* crow = d.C + coff + cb;
                    const float* mrow = d.use_mask ? (d.mask + (long long)(bz >> 3) * d.mzs + cb) : nullptr;
#pragma unroll
                    for (int nt = 0; nt < 8; nt++) {
                        float v0 = acc[mt2][nt][h2 * 2 + 0];
                        float v1 = acc[mt2][nt][h2 * 2 + 1];
                        if (d.use_mask) { v0 = v0 * d.scale + mrow[nt * 8]; v1 = v1 * d.scale + mrow[nt * 8 + 1]; }
                        *reinterpret_cast<float2*>(crow + nt * 8) = make_float2(v0, v1);
                    }
                }
            }
        }
    }
}

// ---------------------------------------------------------------------------
// Megapack: embeds (direct fp16) + weights (smem transpose fp16)
// ---------------------------------------------------------------------------
struct Seg {
    const float* src; __half* dst;
    int nblocks; int mode; int R; int K;
};
struct SegTable { Seg s[10]; };

__global__ void __launch_bounds__(256) megapack(SegTable st)
{
    __shared__ float sm[32][33];
    int b = blockIdx.x, si = 0;
    while (b >= st.s[si].nblocks) { b -= st.s[si].nblocks; si++; }
    const Seg sg = st.s[si];

    if (sg.mode == 0) {
        long long idx = (long long)b * 256 + threadIdx.x;
        int K8 = sg.K >> 3;
        long long items = (long long)sg.R * K8;
        if (idx >= items) return;
        int kc = (int)(idx % K8);
        long long r = idx / K8;
        const float* sp = sg.src + r * (long long)sg.K + kc * 8;
        float4 x = *reinterpret_cast<const float4*>(sp);
        float4 y = *reinterpret_cast<const float4*>(sp + 4);
        float v[8] = {x.x, x.y, x.z, x.w, y.x, y.y, y.z, y.w};
        unsigned short o[8];
#pragma unroll
        for (int i = 0; i < 8; i++) o[i] = __half_as_ushort(__float2half_rn(v[i]));
        uint4 w;
        w.x = o[0] | ((uint32_t)o[1] << 16); w.y = o[2] | ((uint32_t)o[3] << 16);
        w.z = o[4] | ((uint32_t)o[5] << 16); w.w = o[6] | ((uint32_t)o[7] << 16);
        *reinterpret_cast<uint4*>(sg.dst + r * (long long)sg.K + kc * 8) = w;
    } else {
        int nx = sg.K >> 5;
        int k0 = (b % nx) * 32, n0 = (b / nx) * 32;
        int tx = threadIdx.x & 31, ty = threadIdx.x >> 5;
#pragma unroll
        for (int i = 0; i < 4; i++)
            sm[ty + 8 * i][tx] = sg.src[(long long)(k0 + ty + 8 * i) * sg.R + n0 + tx];
        __syncthreads();
#pragma unroll
        for (int i = 0; i < 4; i++) {
            int n = n0 + ty + 8 * i;
            sg.dst[(long long)n * sg.K + k0 + tx] = __float2half_rn(sm[tx][ty + 8 * i]);
        }
    }
}

// ---------------------------------------------------------------------------
// Fused RoPE + fp16 pack of Q (per b,h) and K (per b)
// ---------------------------------------------------------------------------
__global__ void __launch_bounds__(128) qkrope_pack(
    const float* __restrict__ QKV, const int* __restrict__ pos,
    __half* __restrict__ aQ, __half* __restrict__ bK)
{
    const int bl = blockIdx.x;
    const int bidx = bl >> 10, l = bl & 1023;
    const int i = threadIdx.x;
    const float p = (float)pos[bl];
    const float inv = powf(10000.0f, -(float)i * (1.0f / 128.0f));
    float s, c;
    sincosf(p * inv, &s, &c);

    const float* row = QKV + (long long)bl * NQKV;
#pragma unroll
    for (int h = 0; h < Hh; h++) {
        float x1 = row[h * HD + i], x2 = row[h * HD + 128 + i];
        __half* q = aQ + (((long long)(bidx * Hh + h) * Lt + l) * HD);
        q[i]       = __float2half_rn(x1 * c - x2 * s);
        q[128 + i] = __float2half_rn(x2 * c + x1 * s);
    }
    float x1 = row[HH + i], x2 = row[HH + 128 + i];
    __half* kd = bK + ((long long)bidx * Lt + l) * HD;
    kd[i]       = __float2half_rn(x1 * c - x2 * s);
    kd[128 + i] = __float2half_rn(x2 * c + x1 * s);
}

// ---------------------------------------------------------------------------
// V transpose-pack: bV[b][d][Lt]
// ---------------------------------------------------------------------------
__global__ void __launch_bounds__(256) vtpack(const float* __restrict__ QKV,
                                              __half* __restrict__ bV)
{
    __shared__ float sm[32][33];
    const int bidx = blockIdx.z;
    const int l0 = blockIdx.x * 32, d0 = blockIdx.y * 32;
    const int tx = threadIdx.x & 31, ty = threadIdx.x >> 5;
#pragma unroll
    for (int i = 0; i < 4; i++)
        sm[ty + 8 * i][tx] = QKV[((long long)bidx * Lt + l0 + ty + 8 * i) * NQKV + HH + HD + d0 + tx];
    __syncthreads();
#pragma unroll
    for (int i = 0; i < 4; i++) {
        int d = d0 + ty + 8 * i;
        bV[((long long)bidx * HD + d) * Lt + l0 + tx] = __float2half_rn(sm[tx][ty + 8 * i]);
    }
}

// ---------------------------------------------------------------------------
// Softmax over S rows (len 1024) + fp16 P
// ---------------------------------------------------------------------------
__global__ void __launch_bounds__(128) softmax_pack(const float* __restrict__ S,
                                                    __half* __restrict__ P)
{
    __shared__ float red[128];
    const long long rowid = blockIdx.x;
    const float* p = S + rowid * Lt;
    const int t = threadIdx.x, k0 = t * 8;

    float v[8];
    float4 a = *reinterpret_cast<const float4*>(p + k0);
    float4 b = *reinterpret_cast<const float4*>(p + k0 + 4);
    v[0]=a.x; v[1]=a.y; v[2]=a.z; v[3]=a.w; v[4]=b.x; v[5]=b.y; v[6]=b.z; v[7]=b.w;

    float m = v[0];
#pragma unroll
    for (int i = 1; i < 8; i++) m = fmaxf(m, v[i]);
    red[t] = m; __syncthreads();
    for (int s = 64; s > 0; s >>= 1) { if (t < s) red[t] = fmaxf(red[t], red[t + s]); __syncthreads(); }
    m = red[0]; __syncthreads();

    float sum = 0.f;
#pragma unroll
    for (int i = 0; i < 8; i++) { v[i] = expf(v[i] - m); sum += v[i]; }
    red[t] = sum; __syncthreads();
    for (int s = 64; s > 0; s >>= 1) { if (t < s) red[t] += red[t + s]; __syncthreads(); }
    const float invs = 1.0f / red[0];

    unsigned short o[8];
#pragma unroll
    for (int i = 0; i < 8; i++) o[i] = __half_as_ushort(__float2half_rn(v[i] * invs));
    uint4 w;
    w.x = o[0] | ((uint32_t)o[1] << 16); w.y = o[2] | ((uint32_t)o[3] << 16);
    w.z = o[4] | ((uint32_t)o[5] << 16); w.w = o[6] | ((uint32_t)o[7] << 16);
    *reinterpret_cast<uint4*>(P + rowid * Lt + k0) = w;
}

// ---------------------------------------------------------------------------
// Host
// ---------------------------------------------------------------------------
static GZone mkzone(const __half* A, const __half* B, void* C, const float* mask,
                    int nt, int mt, int Z, int K, long long sAz, long long sBz,
                    int zshB, long long cso, long long csi, int czsh, int ldc,
                    float scale, int use_mask, long long mzs, int out_half)
{
    GZone z;
    z.A = A; z.B = B; z.C = (float*)C; z.mask = mask;
    z.sAz = sAz; z.sBz = sBz; z.cso = cso; z.csi = csi; z.mzs = mzs;
    z.K = K; z.zshB = zshB; z.czsh = czsh; z.ldc = ldc;
    z.use_mask = use_mask; z.out_half = out_half;
    z.nt = nt; z.mt = mt; z.tstart = 0;
    z.scale = scale;
    (void)Z;
    return z;
}

static void launch_zones(GZone z0, int n0, GZone z1, int n1, int nz)
{
    GZones g;
    z0.tstart = 0;
    g.z[0] = z0;
    int total = n0;
    if (nz > 1) { z1.tstart = total; g.z[1] = z1; total += n1; }
    else        { g.z[1] = z0; }
    g.nz = nz; g.total = total;
    int grid = total < 304 ? total : 304;
    gemm_hmma<<<grid, 256, GEMM_SMEM>>>(g);
}

extern "C" void kernel_launch(void* const* d_in, const int* in_sizes, int n_in,
                              void* d_out, int out_size)
{
    const float* pali   = (const float*)d_in[0];
    const float* expert = (const float*)d_in[1];
    const int*   pos    = (const int*)d_in[2];
    const float* mask   = (const float*)d_in[3];
    const float* wq_p = (const float*)d_in[5];
    const float* wk_p = (const float*)d_in[6];
    const float* wv_p = (const float*)d_in[7];
    const float* wo_p = (const float*)d_in[8];
    const float* wq_e = (const float*)d_in[9];
    const float* wk_e = (const float*)d_in[10];
    const float* wv_e = (const float*)d_in[11];
    const float* wo_e = (const float*)d_in[12];
    float* out = (float*)d_out;

    cudaFuncSetAttribute(gemm_hmma, cudaFuncAttributeMaxDynamicSharedMemorySize, GEMM_SMEM);

    float *QKV, *S;
    cudaGetSymbolAddress((void**)&QKV, g_QKV);
    cudaGetSymbolAddress((void**)&S,   g_S);
    __half *aP, *aE, *aQ, *aPP, *AO, *bQP, *bQE, *bK, *bV, *bWP, *bWE;
    cudaGetSymbolAddress((void**)&aP,  hA_pali);
    cudaGetSymbolAddress((void**)&aE,  hA_exp);
    cudaGetSymbolAddress((void**)&aQ,  hA_Q);
    cudaGetSymbolAddress((void**)&aPP, hA_P);
    cudaGetSymbolAddress((void**)&AO,  hAO);
    cudaGetSymbolAddress((void**)&bQP, hB_qkvp);
    cudaGetSymbolAddress((void**)&bQE, hB_qkve);
    cudaGetSymbolAddress((void**)&bK,  hB_K);
    cudaGetSymbolAddress((void**)&bV,  hB_V);
    cudaGetSymbolAddress((void**)&bWP, hB_wop);
    cudaGetSymbolAddress((void**)&bWE, hB_woe);

    SegTable st;
    int nb = 0;
    auto setd = [&](int i, const float* s, __half* d, int R, int K) {
        st.s[i] = {s, d, (int)(((long long)R * K / 8 + 255) / 256), 0, R, K};
        nb += st.s[i].nblocks;
    };
    auto sett = [&](int i, const float* s, __half* d, int N, int K) {
        st.s[i] = {s, d, (K / 32) * (N / 32), 1, N, K};
        nb += st.s[i].nblocks;
    };
    setd(0, pali,   aP, Bb * LP, DP);
    setd(1, expert, aE, Bb * LE, DE);
    sett(2, wq_p, bQP,                      HH, DP);
    sett(3, wk_p, bQP + (long long)HH * DP,        HD, DP);
    sett(4, wv_p, bQP + (long long)(HH + HD) * DP, HD, DP);
    sett(5, wq_e, bQE,                      HH, DE);
    sett(6, wk_e, bQE + (long long)HH * DE,        HD, DE);
    sett(7, wv_e, bQE + (long long)(HH + HD) * DE, HD, DE);
    sett(8, wo_p, bWP, DP, HH);
    sett(9, wo_e, bWE, DE, HH);
    megapack<<<nb, 256>>>(st);

    // --- QKV projections (pali + expert merged, one persistent launch) ---
    {
        GZone zp = mkzone(aP, bQP, QKV, nullptr, NQKV / 128, LP / 128, Bb, DP,
                          (long long)LP * DP, 0, 31, (long long)Lt * NQKV, 0, 0, NQKV, 1.f, 0, 0, 0);
        GZone ze = mkzone(aE, bQE, QKV + (long long)LP * NQKV, nullptr, NQKV / 128, LE / 128, Bb, DE,
                          (long long)LE * DE, 0, 31, (long long)Lt * NQKV, 0, 0, NQKV, 1.f, 0, 0, 0);
        launch_zones(zp, (NQKV / 128) * (LP / 128) * Bb, ze, (NQKV / 128) * (LE / 128) * Bb, 2);
    }

    // --- V transpose-pack, fused RoPE + Q/K pack ---
    {
        dim3 g(Lt / 32, HD / 32, Bb);
        vtpack<<<g, 256>>>(QKV, bV);
    }
    qkrope_pack<<<Bb * Lt, 128>>>(QKV, pos, aQ, bK);

    // --- scores = scale*QK^T + mask ---
    {
        GZone zs = mkzone(aQ, bK, S, mask, Lt / 128, Lt / 128, Bb * Hh, HD,
                          (long long)Lt * HD, (long long)Lt * HD, 3,
                          (long long)Lt * Lt, 0, 0, Lt, 0.0625f, 1, (long long)Lt * Lt, 0);
        launch_zones(zs, (Lt / 128) * (Lt / 128) * Bb * Hh, zs, 0, 1);
    }

    // --- softmax -> fp16 P ---
    softmax_pack<<<Bb * Hh * Lt, 128>>>(S, aPP);

    // --- AO = P @ V (fp16 out) ---
    {
        GZone zv = mkzone(aPP, bV, AO, nullptr, HD / 128, Lt / 128, Bb * Hh, Lt,
                          (long long)Lt * Lt, (long long)HD * Lt, 3,
                          (long long)Lt * HH, HD, 3, HH, 1.f, 0, 0, 1);
        launch_zones(zv, (HD / 128) * (Lt / 128) * Bb * Hh, zv, 0, 1);
    }

    // --- output projections (merged) ---
    {
        GZone zo = mkzone(AO, bWP, out, nullptr, DP / 128, LP / 128, Bb, HH,
                          (long long)Lt * HH, 0, 31, (long long)LP * DP, 0, 0, DP, 1.f, 0, 0, 0);
        GZone ze = mkzone(AO + (long long)LP * HH, bWE, out + (long long)Bb * LP * DP, nullptr,
                          DE / 128, LE / 128, Bb, HH,
                          (long long)Lt * HH, 0, 31, (long long)LE * DE, 0, 0, DE, 1.f, 0, 0, 0);
        launch_zones(zo, (DP / 128) * (LP / 128) * Bb, ze, (DE / 128) * (LE / 128) * Bb, 2);
    }
}

// round 10
// speedup vs baseline: 10.7655x; 1.0283x over previous
#include <cuda_runtime.h>
#include <cuda_fp16.h>
#include <math.h>
#include <stdint.h>

constexpr int Bb = 4, LP = 768, LE = 256, Lt = 1024;
constexpr int DP = 2048, DE = 1024, Hh = 8, HD = 256, HH = 2048;
constexpr int NQKV = HH + 2 * HD;  // 2560

// fp32 scratch
__device__ __align__(1024) float g_QKV[(size_t)Bb * Lt * NQKV];
__device__ __align__(1024) float g_S[(size_t)Bb * Hh * Lt * Lt];

// packed fp16 operands, K-major rows [R][K]
__device__ __align__(1024) __half hA_pali[(size_t)Bb * LP * DP];
__device__ __align__(1024) __half hA_exp [(size_t)Bb * LE * DE];
__device__ __align__(1024) __half hA_Q   [(size_t)Bb * Hh * Lt * HD];
__device__ __align__(1024) __half hA_P   [(size_t)Bb * Hh * Lt * Lt];
__device__ __align__(1024) __half hAO    [(size_t)Bb * Lt * HH];
__device__ __align__(1024) __half hB_qkvp[(size_t)NQKV * DP];
__device__ __align__(1024) __half hB_qkve[(size_t)NQKV * DE];
__device__ __align__(1024) __half hB_K   [(size_t)Bb * Lt * HD];
__device__ __align__(1024) __half hB_V   [(size_t)Bb * HD * Lt];
__device__ __align__(1024) __half hB_wop [(size_t)DP * HH];
__device__ __align__(1024) __half hB_woe [(size_t)DE * HH];

__device__ __forceinline__ uint32_t s2u(const void* p) {
    uint32_t a;
    asm("{ .reg .u64 t; cvta.to.shared.u64 t, %1; cvt.u32.u64 %0, t; }" : "=r"(a) : "l"(p));
    return a;
}

#define CP_ASYNC16(saddr, gaddr) \
    asm volatile("cp.async.cg.shared.global [%0], [%1], 16;" :: "r"(saddr), "l"(gaddr))
#define CP_COMMIT() asm volatile("cp.async.commit_group;")
#define CP_WAIT(n)  asm volatile("cp.async.wait_group %0;" :: "n"(n))

#define LDSM4(r, addr)                                                       \
    asm volatile("ldmatrix.sync.aligned.m8n8.x4.shared.b16 {%0,%1,%2,%3}, [%4];" \
        : "=r"((r)[0]), "=r"((r)[1]), "=r"((r)[2]), "=r"((r)[3]) : "r"(addr))

#define MMA16816(c, a, b0, b1)                                               \
    asm volatile("mma.sync.aligned.m16n8k16.row.col.f32.f16.f16.f32 "        \
        "{%0,%1,%2,%3},{%4,%5,%6,%7},{%8,%9},{%0,%1,%2,%3};"                 \
        : "+f"((c)[0]), "+f"((c)[1]), "+f"((c)[2]), "+f"((c)[3])             \
        : "r"((a)[0]), "r"((a)[1]), "r"((a)[2]), "r"((a)[3]), "r"(b0), "r"(b1))

// ---------------------------------------------------------------------------
// Persistent multi-zone HMMA GEMM (TN): 128x128 tiles, BK=64, 8 warps,
// 3-stage cp.async ring, fragment double-buffering, XOR swizzle.
// ---------------------------------------------------------------------------
constexpr int GEMM_SMEM = 98304;

struct GZone {
    const __half* A; const __half* B; float* C; const float* mask;
    long long sAz, sBz, cso, csi, mzs;
    int K, zshB, czsh, ldc, use_mask, out_half, nt, mt, tstart;
    float scale;
};
struct GZones { GZone z[2]; int nz; int total; };

__global__ void __launch_bounds__(256, 2) gemm_hmma(GZones gz)
{
    extern __shared__ __align__(1024) char smem[];
    const uint32_t sbase = s2u(smem);
    const int t = threadIdx.x;
    const int lrow = t >> 3, lc = t & 7;
    const int wid = t >> 5, lane = t & 31;
    const int wm = wid >> 1, wn = wid & 1;
    const int a_r = lane & 15, a_c = lane >> 4;
    const int b_r = (lane & 7) + ((lane >> 4) << 3), b_c = (lane >> 3) & 1;

    for (int tix = blockIdx.x; tix < gz.total; tix += gridDim.x) {
        const int zi = (gz.nz > 1 && tix >= gz.z[1].tstart) ? 1 : 0;
        const GZone& d = gz.z[zi];
        const int lt2 = tix - d.tstart;
        const int bx = lt2 % d.nt;
        const int tmp = lt2 / d.nt;
        const int by = tmp % d.mt, bz = tmp / d.mt;
        const int K = d.K;
        const int nch = K >> 6;

        const __half* Ag = d.A + (long long)bz * d.sAz + (long long)by * 128 * K;
        const __half* Bg = d.B + (long long)(bz >> d.zshB) * d.sBz + (long long)bx * 128 * K;

        float acc[2][8][4];
#pragma unroll
        for (int i = 0; i < 2; i++)
#pragma unroll
            for (int j = 0; j < 8; j++)
#pragma unroll
                for (int k = 0; k < 4; k++) acc[i][j][k] = 0.f;

#define STAGE(s, k0) do {                                                    \
    uint32_t _sA = sbase + (s) * 32768;                                      \
    uint32_t _sB = _sA + 16384;                                              \
    _Pragma("unroll")                                                        \
    for (int _i = 0; _i < 4; _i++) {                                         \
        int _r = lrow + _i * 32;                                             \
        uint32_t _sw = ((uint32_t)(lc ^ (_r & 7))) << 4;                     \
        CP_ASYNC16(_sA + _r * 128 + _sw, Ag + (long long)_r * K + (k0) + lc * 8); \
        CP_ASYNC16(_sB + _r * 128 + _sw, Bg + (long long)_r * K + (k0) + lc * 8); \
    }                                                                        \
    CP_COMMIT();                                                             \
} while (0)

        __syncthreads();  // smem ring reuse across tiles
        STAGE(0, 0);
        if (nch > 1) STAGE(1, 64);

        int slot = 0, slot2 = (nch > 2) ? 2 : 0;
        for (int ch = 0; ch < nch; ch++) {
            if (ch + 1 < nch) CP_WAIT(1); else CP_WAIT(0);
            __syncthreads();
            if (ch + 2 < nch) {
                STAGE(slot2, (ch + 2) << 6);
                slot2 = (slot2 == 2) ? 0 : slot2 + 1;
            }
            uint32_t sA = sbase + slot * 32768;
            uint32_t sB = sA + 16384;
            slot = (slot == 2) ? 0 : slot + 1;

            uint32_t a[2][2][4], b[2][4][4];
            {
#pragma unroll
                for (int mt2 = 0; mt2 < 2; mt2++) {
                    int r = wm * 32 + mt2 * 16 + a_r;
                    LDSM4(a[0][mt2], sA + r * 128 + ((uint32_t)(a_c ^ (r & 7)) << 4));
                }
#pragma unroll
                for (int nt2 = 0; nt2 < 4; nt2++) {
                    int n = wn * 64 + nt2 * 16 + b_r;
                    LDSM4(b[0][nt2], sB + n * 128 + ((uint32_t)(b_c ^ (n & 7)) << 4));
                }
            }
#pragma unroll
            for (int ks = 0; ks < 4; ks++) {
                const int cur = ks & 1, nxt = cur ^ 1;
                if (ks < 3) {
                    const int kc = (ks + 1) << 1;
#pragma unroll
                    for (int mt2 = 0; mt2 < 2; mt2++) {
                        int r = wm * 32 + mt2 * 16 + a_r;
                        LDSM4(a[nxt][mt2], sA + r * 128 + ((uint32_t)((kc + a_c) ^ (r & 7)) << 4));
                    }
#pragma unroll
                    for (int nt2 = 0; nt2 < 4; nt2++) {
                        int n = wn * 64 + nt2 * 16 + b_r;
                        LDSM4(b[nxt][nt2], sB + n * 128 + ((uint32_t)((kc + b_c) ^ (n & 7)) << 4));
                    }
                }
#pragma unroll
                for (int mt2 = 0; mt2 < 2; mt2++)
#pragma unroll
                    for (int nt = 0; nt < 8; nt++)
                        MMA16816(acc[mt2][nt], a[cur][mt2],
                                 b[cur][nt >> 1][(nt & 1) * 2], b[cur][nt >> 1][(nt & 1) * 2 + 1]);
            }
        }
#undef STAGE

        const long long coff = ((long long)(bz >> d.czsh)) * d.cso +
                               (long long)(bz & ((1 << d.czsh) - 1)) * d.csi;
        const int g = lane >> 2, tig = lane & 3;
#pragma unroll
        for (int mt2 = 0; mt2 < 2; mt2++) {
#pragma unroll
            for (int h2 = 0; h2 < 2; h2++) {
                long long row = (long long)by * 128 + wm * 32 + mt2 * 16 + g + h2 * 8;
                long long cb = row * (long long)d.ldc + (long long)bx * 128 + wn * 64 + tig * 2;
                if (d.out_half) {
                    __half* crow = reinterpret_cast<__half*>(d.C) + coff + cb;
#pragma unroll
                    for (int nt = 0; nt < 8; nt++) {
                        __half h0 = __float2half_rn(acc[mt2][nt][h2 * 2 + 0]);
                        __half h1 = __float2half_rn(acc[mt2][nt][h2 * 2 + 1]);
                        *reinterpret_cast<__half2*>(crow + nt * 8) = __halves2half2(h0, h1);
                    }
                } else {
                    float* crow = d.C + coff + cb;
                    const float* mrow = d.use_mask ? (d.mask + (long long)(bz >> 3) * d.mzs + cb) : nullptr;
#pragma unroll
                    for (int nt = 0; nt < 8; nt++) {
                        float v0 = acc[mt2][nt][h2 * 2 + 0];
                        float v1 = acc[mt2][nt][h2 * 2 + 1];
                        if (d.use_mask) { v0 = v0 * d.scale + mrow[nt * 8]; v1 = v1 * d.scale + mrow[nt * 8 + 1]; }
                        *reinterpret_cast<float2*>(crow + nt * 8) = make_float2(v0, v1);
                    }
                }
            }
        }
    }
}

// ---------------------------------------------------------------------------
// Megapack: embeds (direct fp16) + weights (smem transpose fp16)
// ---------------------------------------------------------------------------
struct Seg {
    const float* src; __half* dst;
    int nblocks; int mode; int R; int K;
};
struct SegTable { Seg s[10]; };

__global__ void __launch_bounds__(256) megapack(SegTable st)
{
    __shared__ float sm[32][33];
    int b = blockIdx.x, si = 0;
    while (b >= st.s[si].nblocks) { b -= st.s[si].nblocks; si++; }
    const Seg sg = st.s[si];

    if (sg.mode == 0) {
        long long idx = (long long)b * 256 + threadIdx.x;
        int K8 = sg.K >> 3;
        long long items = (long long)sg.R * K8;
        if (idx >= items) return;
        int kc = (int)(idx % K8);
        long long r = idx / K8;
        const float* sp = sg.src + r * (long long)sg.K + kc * 8;
        float4 x = *reinterpret_cast<const float4*>(sp);
        float4 y = *reinterpret_cast<const float4*>(sp + 4);
        float v[8] = {x.x, x.y, x.z, x.w, y.x, y.y, y.z, y.w};
        unsigned short o[8];
#pragma unroll
        for (int i = 0; i < 8; i++) o[i] = __half_as_ushort(__float2half_rn(v[i]));
        uint4 w;
        w.x = o[0] | ((uint32_t)o[1] << 16); w.y = o[2] | ((uint32_t)o[3] << 16);
        w.z = o[4] | ((uint32_t)o[5] << 16); w.w = o[6] | ((uint32_t)o[7] << 16);
        *reinterpret_cast<uint4*>(sg.dst + r * (long long)sg.K + kc * 8) = w;
    } else {
        int nx = sg.K >> 5;
        int k0 = (b % nx) * 32, n0 = (b / nx) * 32;
        int tx = threadIdx.x & 31, ty = threadIdx.x >> 5;
#pragma unroll
        for (int i = 0; i < 4; i++)
            sm[ty + 8 * i][tx] = sg.src[(long long)(k0 + ty + 8 * i) * sg.R + n0 + tx];
        __syncthreads();
#pragma unroll
        for (int i = 0; i < 4; i++) {
            int n = n0 + ty + 8 * i;
            sg.dst[(long long)n * sg.K + k0 + tx] = __float2half_rn(sm[tx][ty + 8 * i]);
        }
    }
}

// ---------------------------------------------------------------------------
// Fused RoPE + fp16 pack of Q (per b,h) and K (per b)
// ---------------------------------------------------------------------------
__global__ void __launch_bounds__(128) qkrope_pack(
    const float* __restrict__ QKV, const int* __restrict__ pos,
    __half* __restrict__ aQ, __half* __restrict__ bK)
{
    const int bl = blockIdx.x;
    const int bidx = bl >> 10, l = bl & 1023;
    const int i = threadIdx.x;
    const float p = (float)pos[bl];
    const float inv = powf(10000.0f, -(float)i * (1.0f / 128.0f));
    float s, c;
    sincosf(p * inv, &s, &c);

    const float* row = QKV + (long long)bl * NQKV;
#pragma unroll
    for (int h = 0; h < Hh; h++) {
        float x1 = row[h * HD + i], x2 = row[h * HD + 128 + i];
        __half* q = aQ + (((long long)(bidx * Hh + h) * Lt + l) * HD);
        q[i]       = __float2half_rn(x1 * c - x2 * s);
        q[128 + i] = __float2half_rn(x2 * c + x1 * s);
    }
    float x1 = row[HH + i], x2 = row[HH + 128 + i];
    __half* kd = bK + ((long long)bidx * Lt + l) * HD;
    kd[i]       = __float2half_rn(x1 * c - x2 * s);
    kd[128 + i] = __float2half_rn(x2 * c + x1 * s);
}

// ---------------------------------------------------------------------------
// V transpose-pack: bV[b][d][Lt]
// ---------------------------------------------------------------------------
__global__ void __launch_bounds__(256) vtpack(const float* __restrict__ QKV,
                                              __half* __restrict__ bV)
{
    __shared__ float sm[32][33];
    const int bidx = blockIdx.z;
    const int l0 = blockIdx.x * 32, d0 = blockIdx.y * 32;
    const int tx = threadIdx.x & 31, ty = threadIdx.x >> 5;
#pragma unroll
    for (int i = 0; i < 4; i++)
        sm[ty + 8 * i][tx] = QKV[((long long)bidx * Lt + l0 + ty + 8 * i) * NQKV + HH + HD + d0 + tx];
    __syncthreads();
#pragma unroll
    for (int i = 0; i < 4; i++) {
        int d = d0 + ty + 8 * i;
        bV[((long long)bidx * HD + d) * Lt + l0 + tx] = __float2half_rn(sm[tx][ty + 8 * i]);
    }
}

// ---------------------------------------------------------------------------
// Softmax: warp-per-row, shuffle reductions only, __expf, float4 I/O.
// 8 rows per 256-thread block. Rows of length 1024.
// ---------------------------------------------------------------------------
__global__ void __launch_bounds__(256) softmax_pack(const float* __restrict__ S,
                                                    __half* __restrict__ P)
{
    const long long rowid = (long long)blockIdx.x * 8 + (threadIdx.x >> 5);
    const int lane = threadIdx.x & 31;
    const float* p = S + rowid * Lt + lane * 4;

    float v[32];
#pragma unroll
    for (int c = 0; c < 8; c++) {
        float4 x = *reinterpret_cast<const float4*>(p + c * 128);
        v[c * 4 + 0] = x.x; v[c * 4 + 1] = x.y; v[c * 4 + 2] = x.z; v[c * 4 + 3] = x.w;
    }

    float m = v[0];
#pragma unroll
    for (int i = 1; i < 32; i++) m = fmaxf(m, v[i]);
#pragma unroll
    for (int o = 16; o > 0; o >>= 1)
        m = fmaxf(m, __shfl_xor_sync(0xFFFFFFFFu, m, o));

    float sum = 0.f;
#pragma unroll
    for (int i = 0; i < 32; i++) { v[i] = __expf(v[i] - m); sum += v[i]; }
#pragma unroll
    for (int o = 16; o > 0; o >>= 1)
        sum += __shfl_xor_sync(0xFFFFFFFFu, sum, o);
    const float invs = 1.0f / sum;

    __half* dp = P + rowid * Lt + lane * 4;
#pragma unroll
    for (int c = 0; c < 8; c++) {
        __half2 h0 = __halves2half2(__float2half_rn(v[c * 4 + 0] * invs),
                                    __float2half_rn(v[c * 4 + 1] * invs));
        __half2 h1 = __halves2half2(__float2half_rn(v[c * 4 + 2] * invs),
                                    __float2half_rn(v[c * 4 + 3] * invs));
        uint2 w;
        w.x = *reinterpret_cast<uint32_t*>(&h0);
        w.y = *reinterpret_cast<uint32_t*>(&h1);
        *reinterpret_cast<uint2*>(dp + c * 128) = w;
    }
}

// ---------------------------------------------------------------------------
// Host
// ---------------------------------------------------------------------------
static GZone mkzone(const __half* A, const __half* B, void* C, const float* mask,
                    int nt, int mt, int K, long long sAz, long long sBz,
                    int zshB, long long cso, long long csi, int czsh, int ldc,
                    float scale, int use_mask, long long mzs, int out_half)
{
    GZone z;
    z.A = A; z.B = B; z.C = (float*)C; z.mask = mask;
    z.sAz = sAz; z.sBz = sBz; z.cso = cso; z.csi = csi; z.mzs = mzs;
    z.K = K; z.zshB = zshB; z.czsh = czsh; z.ldc = ldc;
    z.use_mask = use_mask; z.out_half = out_half;
    z.nt = nt; z.mt = mt; z.tstart = 0;
    z.scale = scale;
    return z;
}

static void launch_zones(GZone z0, int n0, GZone z1, int n1, int nz)
{
    GZones g;
    z0.tstart = 0;
    g.z[0] = z0;
    int total = n0;
    if (nz > 1) { z1.tstart = total; g.z[1] = z1; total += n1; }
    else        { g.z[1] = z0; }
    g.nz = nz; g.total = total;
    int grid = total < 304 ? total : 304;
    gemm_hmma<<<grid, 256, GEMM_SMEM>>>(g);
}

extern "C" void kernel_launch(void* const* d_in, const int* in_sizes, int n_in,
                              void* d_out, int out_size)
{
    const float* pali   = (const float*)d_in[0];
    const float* expert = (const float*)d_in[1];
    const int*   pos    = (const int*)d_in[2];
    const float* mask   = (const float*)d_in[3];
    const float* wq_p = (const float*)d_in[5];
    const float* wk_p = (const float*)d_in[6];
    const float* wv_p = (const float*)d_in[7];
    const float* wo_p = (const float*)d_in[8];
    const float* wq_e = (const float*)d_in[9];
    const float* wk_e = (const float*)d_in[10];
    const float* wv_e = (const float*)d_in[11];
    const float* wo_e = (const float*)d_in[12];
    float* out = (float*)d_out;

    cudaFuncSetAttribute(gemm_hmma, cudaFuncAttributeMaxDynamicSharedMemorySize, GEMM_SMEM);

    float *QKV, *S;
    cudaGetSymbolAddress((void**)&QKV, g_QKV);
    cudaGetSymbolAddress((void**)&S,   g_S);
    __half *aP, *aE, *aQ, *aPP, *AO, *bQP, *bQE, *bK, *bV, *bWP, *bWE;
    cudaGetSymbolAddress((void**)&aP,  hA_pali);
    cudaGetSymbolAddress((void**)&aE,  hA_exp);
    cudaGetSymbolAddress((void**)&aQ,  hA_Q);
    cudaGetSymbolAddress((void**)&aPP, hA_P);
    cudaGetSymbolAddress((void**)&AO,  hAO);
    cudaGetSymbolAddress((void**)&bQP, hB_qkvp);
    cudaGetSymbolAddress((void**)&bQE, hB_qkve);
    cudaGetSymbolAddress((void**)&bK,  hB_K);
    cudaGetSymbolAddress((void**)&bV,  hB_V);
    cudaGetSymbolAddress((void**)&bWP, hB_wop);
    cudaGetSymbolAddress((void**)&bWE, hB_woe);

    SegTable st;
    int nb = 0;
    auto setd = [&](int i, const float* s, __half* d, int R, int K) {
        st.s[i] = {s, d, (int)(((long long)R * K / 8 + 255) / 256), 0, R, K};
        nb += st.s[i].nblocks;
    };
    auto sett = [&](int i, const float* s, __half* d, int N, int K) {
        st.s[i] = {s, d, (K / 32) * (N / 32), 1, N, K};
        nb += st.s[i].nblocks;
    };
    setd(0, pali,   aP, Bb * LP, DP);
    setd(1, expert, aE, Bb * LE, DE);
    sett(2, wq_p, bQP,                      HH, DP);
    sett(3, wk_p, bQP + (long long)HH * DP,        HD, DP);
    sett(4, wv_p, bQP + (long long)(HH + HD) * DP, HD, DP);
    sett(5, wq_e, bQE,                      HH, DE);
    sett(6, wk_e, bQE + (long long)HH * DE,        HD, DE);
    sett(7, wv_e, bQE + (long long)(HH + HD) * DE, HD, DE);
    sett(8, wo_p, bWP, DP, HH);
    sett(9, wo_e, bWE, DE, HH);
    megapack<<<nb, 256>>>(st);  // launch 1

    // --- QKV projections (merged) ---  launch 2
    {
        GZone zp = mkzone(aP, bQP, QKV, nullptr, NQKV / 128, LP / 128, DP,
                          (long long)LP * DP, 0, 31, (long long)Lt * NQKV, 0, 0, NQKV, 1.f, 0, 0, 0);
        GZone ze = mkzone(aE, bQE, QKV + (long long)LP * NQKV, nullptr, NQKV / 128, LE / 128, DE,
                          (long long)LE * DE, 0, 31, (long long)Lt * NQKV, 0, 0, NQKV, 1.f, 0, 0, 0);
        launch_zones(zp, (NQKV / 128) * (LP / 128) * Bb, ze, (NQKV / 128) * (LE / 128) * Bb, 2);
    }

    // --- fused RoPE + Q/K pack ---  launch 3
    qkrope_pack<<<Bb * Lt, 128>>>(QKV, pos, aQ, bK);

    // --- scores = scale*QK^T + mask ---  launch 4 (ncu-profiled slot)
    {
        GZone zs = mkzone(aQ, bK, S, mask, Lt / 128, Lt / 128, HD,
                          (long long)Lt * HD, (long long)Lt * HD, 3,
                          (long long)Lt * Lt, 0, 0, Lt, 0.0625f, 1, (long long)Lt * Lt, 0);
        launch_zones(zs, (Lt / 128) * (Lt / 128) * Bb * Hh, zs, 0, 1);
    }

    // --- V transpose-pack (only needed by PV) ---  launch 5
    {
        dim3 g(Lt / 32, HD / 32, Bb);
        vtpack<<<g, 256>>>(QKV, bV);
    }

    // --- softmax -> fp16 P ---  launch 6
    softmax_pack<<<Bb * Hh * Lt / 8, 256>>>(S, aPP);

    // --- AO = P @ V (fp16 out) ---  launch 7
    {
        GZone zv = mkzone(aPP, bV, AO, nullptr, HD / 128, Lt / 128, Lt,
                          (long long)Lt * Lt, (long long)HD * Lt, 3,
                          (long long)Lt * HH, HD, 3, HH, 1.f, 0, 0, 1);
        launch_zones(zv, (HD / 128) * (Lt / 128) * Bb * Hh, zv, 0, 1);
    }

    // --- output projections (merged) ---  launch 8
    {
        GZone zo = mkzone(AO, bWP, out, nullptr, DP / 128, LP / 128, HH,
                          (long long)Lt * HH, 0, 31, (long long)LP * DP, 0, 0, DP, 1.f, 0, 0, 0);
        GZone ze = mkzone(AO + (long long)LP * HH, bWE, out + (long long)Bb * LP * DP, nullptr,
                          DE / 128, LE / 128, HH,
                          (long long)Lt * HH, 0, 31, (long long)LE * DE, 0, 0, DE, 1.f, 0, 0, 0);
        launch_zones(zo, (DP / 128) * (LP / 128) * Bb, ze, (DE / 128) * (LE / 128) * Bb, 2);
    }
}